// round 2
// baseline (speedup 1.0000x reference)
#include <cuda_runtime.h>
#include <cuda_bf16.h>
#include <cooperative_groups.h>
#include <cstdint>
#include <cstddef>

namespace cg = cooperative_groups;

#define HID   256
#define T_SEQ 1024
#define NB    64

// ---------------- scratch (device globals; no allocation) ----------------
__device__ float g_h1[(size_t)NB * T_SEQ * 512];          // layer-0 output [b][t][512] (fwd|bwd)
__device__ float g_gx[(size_t)2 * T_SEQ * NB * 1024];     // layer-1 projected gates [dir][t][b][1024]
__device__ float g_feat[NB * 512];                        // features at t=L-1
__device__ float g_y[NB * 256];                           // fc1 output

__device__ __forceinline__ float sigf(float x) {
    return __fdividef(1.0f, 1.0f + __expf(-x));
}

// =====================================================================
// Recurrent LSTM: cluster of 8 CTAs per (dir, batch-group-of-8).
// CTA = 256 threads. Thread (lane=unit u, warp=k-slice) holds W_hh slice
// in registers: 4 gates x 32 k = 128 floats. Per step:
//   partial matvec (8 batches) -> SMEM reduce -> gates (thread b=warp,u=lane)
//   -> publish slice -> cluster.sync -> DSMEM gather full h.
// =====================================================================
template<int LAYER>
__global__ void __launch_bounds__(256, 1) __cluster_dims__(8, 1, 1)
lstm_rec(const float* __restrict__ x, const int* __restrict__ lengths,
         const float* __restrict__ Wih, const float* __restrict__ Whh,
         const float* __restrict__ bih, const float* __restrict__ bhh)
{
    __shared__ __align__(16) float hbuf[8 * 256];       // full h for 8 batches
    __shared__ __align__(16) float slice[2 * 8 * 32];   // double-buffered own slice [p][b][u]
    __shared__ __align__(16) float part[8 * 8 * 32 * 4];// partials [w][b][u][gate]

    cg::cluster_group cluster = cg::this_cluster();
    const int tid   = threadIdx.x;
    const int warp  = tid >> 5;
    const int lane  = tid & 31;
    const int crank = blockIdx.x & 7;
    const int group = blockIdx.x >> 3;   // 16 groups
    const int dir   = group >> 3;        // 0 fwd, 1 bwd
    const int bg    = group & 7;         // batch group
    const int ubase = crank * 32;
    const int uglob = ubase + lane;
    const int bglob = bg * 8 + warp;     // this thread's reducer batch
    const int L     = lengths[bglob];

    // ---- W_hh slice into registers: wreg[gate][k_local], k = warp*32 + k_local
    float wreg[4][32];
    #pragma unroll
    for (int g = 0; g < 4; g++) {
        const float* wp = Whh + ((size_t)(dir * 1024 + g * 256 + uglob)) * 256 + warp * 32;
        #pragma unroll
        for (int q = 0; q < 8; q++) {
            float4 v = *reinterpret_cast<const float4*>(wp + q * 4);
            wreg[g][q * 4 + 0] = v.x; wreg[g][q * 4 + 1] = v.y;
            wreg[g][q * 4 + 2] = v.z; wreg[g][q * 4 + 3] = v.w;
        }
    }

    // ---- layer-0 per-thread input projection params (IN = 3)
    float wia[4], wib[4], wic[4], bs4[4];
    if (LAYER == 0) {
        #pragma unroll
        for (int g = 0; g < 4; g++) {
            int row = dir * 1024 + g * 256 + uglob;
            wia[g] = Wih[(size_t)row * 3 + 0];
            wib[g] = Wih[(size_t)row * 3 + 1];
            wic[g] = Wih[(size_t)row * 3 + 2];
            bs4[g] = bih[row] + bhh[row];
        }
    }

    for (int i = tid; i < 8 * 256; i += 256) hbuf[i] = 0.0f;
    __syncthreads();

    // ---- DSMEM gather mapping: thread copies 2 float4 from peer xc, batch xb
    const int xb = tid >> 5;
    const int xi = tid & 31;
    const int xc = xi >> 2;   // peer CTA rank 0..7
    const int xq = xi & 3;    // quad 0..3 (and xq+4)

    float c = 0.0f, h = 0.0f;

    for (int t = 0; t < T_SEQ; t++) {
        const bool m = (t < L);

        // ---- prefetch gate pre-activations (input part) for reducer (b=warp, u=lane)
        float p0, p1, p2, p3;
        if (LAYER == 0) {
            int teff = (dir == 0) ? t : (m ? (L - 1 - t) : t);
            const float* xp = x + ((size_t)bglob * T_SEQ + teff) * 3;
            float x0 = xp[0], x1 = xp[1], x2 = xp[2];
            p0 = bs4[0] + wia[0] * x0 + wib[0] * x1 + wic[0] * x2;
            p1 = bs4[1] + wia[1] * x0 + wib[1] * x1 + wic[1] * x2;
            p2 = bs4[2] + wia[2] * x0 + wib[2] * x1 + wic[2] * x2;
            p3 = bs4[3] + wia[3] * x0 + wib[3] * x1 + wic[3] * x2;
        } else {
            const float* gp = g_gx + (((size_t)dir * T_SEQ + t) * NB + bglob) * 1024 + uglob;
            p0 = __ldg(gp);       p1 = __ldg(gp + 256);
            p2 = __ldg(gp + 512); p3 = __ldg(gp + 768);
        }

        // ---- partial matvec: this thread's (unit=lane, k-slice=warp) for all 8 batches
        #pragma unroll
        for (int b = 0; b < 8; b++) {
            float a0 = 0.f, a1 = 0.f, a2 = 0.f, a3 = 0.f;
            const float* hb = hbuf + b * 256 + warp * 32;
            #pragma unroll
            for (int q = 0; q < 8; q++) {
                float4 hv = *reinterpret_cast<const float4*>(hb + q * 4);
                a0 = fmaf(wreg[0][q * 4 + 0], hv.x, a0);
                a0 = fmaf(wreg[0][q * 4 + 1], hv.y, a0);
                a0 = fmaf(wreg[0][q * 4 + 2], hv.z, a0);
                a0 = fmaf(wreg[0][q * 4 + 3], hv.w, a0);
                a1 = fmaf(wreg[1][q * 4 + 0], hv.x, a1);
                a1 = fmaf(wreg[1][q * 4 + 1], hv.y, a1);
                a1 = fmaf(wreg[1][q * 4 + 2], hv.z, a1);
                a1 = fmaf(wreg[1][q * 4 + 3], hv.w, a1);
                a2 = fmaf(wreg[2][q * 4 + 0], hv.x, a2);
                a2 = fmaf(wreg[2][q * 4 + 1], hv.y, a2);
                a2 = fmaf(wreg[2][q * 4 + 2], hv.z, a2);
                a2 = fmaf(wreg[2][q * 4 + 3], hv.w, a2);
                a3 = fmaf(wreg[3][q * 4 + 0], hv.x, a3);
                a3 = fmaf(wreg[3][q * 4 + 1], hv.y, a3);
                a3 = fmaf(wreg[3][q * 4 + 2], hv.z, a3);
                a3 = fmaf(wreg[3][q * 4 + 3], hv.w, a3);
            }
            *reinterpret_cast<float4*>(&part[((warp * 8 + b) * 32 + lane) * 4]) =
                make_float4(a0, a1, a2, a3);
        }
        __syncthreads();

        // ---- reduce over 8 k-slices: reducer (b = warp, u = lane)
        float g0 = p0, g1 = p1, g2 = p2, g3 = p3;
        #pragma unroll
        for (int w2 = 0; w2 < 8; w2++) {
            float4 v = *reinterpret_cast<const float4*>(&part[((w2 * 8 + warp) * 32 + lane) * 4]);
            g0 += v.x; g1 += v.y; g2 += v.z; g3 += v.w;
        }
        float ig = sigf(g0), fg = sigf(g1);
        float gg = tanhf(g2), og = sigf(g3);
        float cn = fmaf(fg, c, ig * gg);
        float hn = og * tanhf(cn);
        if (m) { c = cn; h = hn; }

        if (LAYER == 0) {
            int pos = (dir == 0) ? t : (m ? (L - 1 - t) : t);
            g_h1[((size_t)bglob * T_SEQ + pos) * 512 + dir * 256 + uglob] = m ? h : 0.0f;
        } else if (dir == 1 && t == 0) {
            g_feat[bglob * 512 + 256 + uglob] = h;   // bwd feature = bwd_r at t=0
        }

        // ---- publish slice, cluster-sync, gather full h
        const int p = t & 1;
        slice[p * 256 + warp * 32 + lane] = h;
        cluster.sync();
        {
            float* psl = cluster.map_shared_rank((float*)slice, (unsigned)xc);
            const float* src = psl + p * 256 + xb * 32 + xq * 4;
            float4 v0 = *reinterpret_cast<const float4*>(src);
            float4 v1 = *reinterpret_cast<const float4*>(src + 16);
            *reinterpret_cast<float4*>(hbuf + xb * 256 + xc * 32 + xq * 4)      = v0;
            *reinterpret_cast<float4*>(hbuf + xb * 256 + xc * 32 + xq * 4 + 16) = v1;
        }
        __syncthreads();
    }

    if (LAYER == 1 && dir == 0)
        g_feat[bglob * 512 + uglob] = h;             // fwd feature = final (frozen) h
}

// =====================================================================
// Layer-1 input projection: gx[dir][t][b][n] = bias + h1[b][teff] . W_ih1[dir][n]
// Tile 64(b) x 128(n), K = 512, BK = 16, 256 threads, 8x4 per-thread.
// =====================================================================
__global__ void __launch_bounds__(256) gx_gemm(
    const int* __restrict__ lengths, const float* __restrict__ Wih,
    const float* __restrict__ bih, const float* __restrict__ bhh)
{
    __shared__ __align__(16) float As[16][68];
    __shared__ __align__(16) float Bs[16][132];
    __shared__ const float* aptr[64];
    __shared__ float bias_s[128];

    const int tid = threadIdx.x;
    const int t   = blockIdx.y;
    const int dir = blockIdx.z;
    const int n0  = blockIdx.x * 128;

    if (tid < 64) {
        int L = lengths[tid];
        int teff = (dir == 0) ? t : ((t < L) ? (L - 1 - t) : t);
        aptr[tid] = g_h1 + ((size_t)tid * T_SEQ + teff) * 512;
    }
    if (tid < 128) {
        int row = dir * 1024 + n0 + tid;
        bias_s[tid] = bih[row] + bhh[row];
    }
    __syncthreads();

    const int am = tid >> 2, ak = (tid & 3) << 2;
    const int bn = tid >> 1, bk = (tid & 1) << 3;
    const float* Ap = aptr[am];
    const float* Bp = Wih + (size_t)(dir * 1024 + n0 + bn) * 512;
    const int tx = tid & 31, ty = tid >> 5;

    float acc[8][4];
    #pragma unroll
    for (int i = 0; i < 8; i++)
        #pragma unroll
        for (int j = 0; j < 4; j++) acc[i][j] = 0.0f;

    float4 av  = *reinterpret_cast<const float4*>(Ap + ak);
    float4 b0v = *reinterpret_cast<const float4*>(Bp + bk);
    float4 b1v = *reinterpret_cast<const float4*>(Bp + bk + 4);

    for (int k0 = 0; k0 < 512; k0 += 16) {
        As[ak + 0][am] = av.x;  As[ak + 1][am] = av.y;
        As[ak + 2][am] = av.z;  As[ak + 3][am] = av.w;
        Bs[bk + 0][bn] = b0v.x; Bs[bk + 1][bn] = b0v.y;
        Bs[bk + 2][bn] = b0v.z; Bs[bk + 3][bn] = b0v.w;
        Bs[bk + 4][bn] = b1v.x; Bs[bk + 5][bn] = b1v.y;
        Bs[bk + 6][bn] = b1v.z; Bs[bk + 7][bn] = b1v.w;
        __syncthreads();

        if (k0 + 16 < 512) {    // prefetch next tile
            av  = *reinterpret_cast<const float4*>(Ap + k0 + 16 + ak);
            b0v = *reinterpret_cast<const float4*>(Bp + k0 + 16 + bk);
            b1v = *reinterpret_cast<const float4*>(Bp + k0 + 16 + bk + 4);
        }

        #pragma unroll
        for (int kk = 0; kk < 16; kk++) {
            float4 aA = *reinterpret_cast<const float4*>(&As[kk][ty * 8]);
            float4 aB = *reinterpret_cast<const float4*>(&As[kk][ty * 8 + 4]);
            float a[8] = {aA.x, aA.y, aA.z, aA.w, aB.x, aB.y, aB.z, aB.w};
            float bv[4];
            #pragma unroll
            for (int j = 0; j < 4; j++) bv[j] = Bs[kk][tx + 32 * j];
            #pragma unroll
            for (int i = 0; i < 8; i++)
                #pragma unroll
                for (int j = 0; j < 4; j++)
                    acc[i][j] = fmaf(a[i], bv[j], acc[i][j]);
        }
        __syncthreads();
    }

    float* gxp = g_gx + ((size_t)(dir * T_SEQ + t) * NB) * 1024 + n0;
    #pragma unroll
    for (int i = 0; i < 8; i++) {
        int mrow = ty * 8 + i;
        #pragma unroll
        for (int j = 0; j < 4; j++)
            gxp[(size_t)mrow * 1024 + tx + 32 * j] = acc[i][j] + bias_s[tx + 32 * j];
    }
}

// =====================================================================
// Head: fc1+relu -> batchnorm(batch axis) -> fc_out
// =====================================================================
__global__ void __launch_bounds__(256) head_fc1(const float* __restrict__ fc1_w,
                                                const float* __restrict__ fc1_b)
{
    __shared__ __align__(16) float fs[512];
    int b = blockIdx.x, n = threadIdx.x;
    for (int i = n; i < 512; i += 256) fs[i] = g_feat[b * 512 + i];
    __syncthreads();
    const float4* wp = reinterpret_cast<const float4*>(fc1_w + (size_t)n * 512);
    const float4* fp = reinterpret_cast<const float4*>(fs);
    float acc = fc1_b[n];
    #pragma unroll 4
    for (int k = 0; k < 128; k++) {
        float4 w4 = __ldg(wp + k);
        float4 f4 = fp[k];
        acc += w4.x * f4.x + w4.y * f4.y + w4.z * f4.z + w4.w * f4.w;
    }
    g_y[b * 256 + n] = fmaxf(acc, 0.0f);
}

__global__ void head_bn(const float* __restrict__ gamma, const float* __restrict__ beta)
{
    int n = threadIdx.x;
    float s = 0.0f, s2 = 0.0f;
    for (int b = 0; b < 64; b++) {
        float v = g_y[b * 256 + n];
        s += v; s2 += v * v;
    }
    float mean = s * 0.015625f;
    float var  = s2 * 0.015625f - mean * mean;
    float inv  = rsqrtf(var + 1e-5f);
    float ga = gamma[n] * inv, be = beta[n];
    for (int b = 0; b < 64; b++)
        g_y[b * 256 + n] = (g_y[b * 256 + n] - mean) * ga + be;
}

__global__ void __launch_bounds__(256) head_out(const float* __restrict__ W,
                                                const float* __restrict__ bias,
                                                float* __restrict__ out)
{
    __shared__ __align__(16) float ys[256];
    int b = blockIdx.x;
    ys[threadIdx.x] = g_y[b * 256 + threadIdx.x];
    __syncthreads();
    int o = threadIdx.x;
    if (o < 196) {
        const float4* wp = reinterpret_cast<const float4*>(W + (size_t)o * 256);
        const float4* yp = reinterpret_cast<const float4*>(ys);
        float acc = bias[o];
        #pragma unroll 4
        for (int k = 0; k < 64; k++) {
            float4 w4 = __ldg(wp + k);
            float4 y4 = yp[k];
            acc += w4.x * y4.x + w4.y * y4.y + w4.z * y4.z + w4.w * y4.w;
        }
        out[(size_t)b * 196 + o] = acc;
    }
}

// =====================================================================
extern "C" void kernel_launch(void* const* d_in, const int* in_sizes, int n_in,
                              void* d_out, int out_size)
{
    const float* x       = (const float*)d_in[0];
    const int*   lengths = (const int*)  d_in[1];
    const float* Wih0    = (const float*)d_in[2];
    const float* Whh0    = (const float*)d_in[3];
    const float* bih0    = (const float*)d_in[4];
    const float* bhh0    = (const float*)d_in[5];
    const float* Wih1    = (const float*)d_in[6];
    const float* Whh1    = (const float*)d_in[7];
    const float* bih1    = (const float*)d_in[8];
    const float* bhh1    = (const float*)d_in[9];
    const float* fc1_w   = (const float*)d_in[10];
    const float* fc1_b   = (const float*)d_in[11];
    const float* gamma   = (const float*)d_in[12];
    const float* beta    = (const float*)d_in[13];
    const float* fcow    = (const float*)d_in[14];
    const float* fcob    = (const float*)d_in[15];
    float* out = (float*)d_out;

    lstm_rec<0><<<128, 256>>>(x, lengths, Wih0, Whh0, bih0, bhh0);
    gx_gemm<<<dim3(8, 1024, 2), 256>>>(lengths, Wih1, bih1, bhh1);
    lstm_rec<1><<<128, 256>>>(x, lengths, Wih1, Whh1, bih1, bhh1);
    head_fc1<<<64, 256>>>(fc1_w, fc1_b);
    head_bn<<<1, 256>>>(gamma, beta);
    head_out<<<64, 256>>>(fcow, fcob, out);
}

// round 4
// speedup vs baseline: 1.1219x; 1.1219x over previous
#include <cuda_runtime.h>
#include <cuda_bf16.h>
#include <cooperative_groups.h>
#include <cstdint>
#include <cstddef>

namespace cg = cooperative_groups;

#define HID   256
#define T_SEQ 1024
#define NB    64

// ---------------- scratch (device globals; no allocation) ----------------
__device__ __nv_bfloat16 g_h1h[(size_t)NB * T_SEQ * 512];   // layer-0 out, bf16 hi
__device__ __nv_bfloat16 g_h1l[(size_t)NB * T_SEQ * 512];   // layer-0 out, bf16 lo
__device__ __nv_bfloat16 g_w1h[(size_t)2 * 1024 * 512];     // W_ih_l1 bf16 hi
__device__ __nv_bfloat16 g_w1l[(size_t)2 * 1024 * 512];     // W_ih_l1 bf16 lo
__device__ float g_gx[(size_t)2 * T_SEQ * NB * 1024];       // layer-1 projected gates
__device__ float g_feat[NB * 512];
__device__ float g_y[NB * 256];

__device__ __forceinline__ float sigf(float x) {
    return __fdividef(1.0f, 1.0f + __expf(-x));
}

// mma.sync m16n8k16 row.col bf16 -> f32 (plain PTX, works on generic sm_103 target)
__device__ __forceinline__ void mma_bf16(float* c, const uint32_t* a,
                                         uint32_t b0, uint32_t b1) {
    asm volatile(
        "mma.sync.aligned.m16n8k16.row.col.f32.bf16.bf16.f32 "
        "{%0,%1,%2,%3}, {%4,%5,%6,%7}, {%8,%9}, {%0,%1,%2,%3};"
        : "+f"(c[0]), "+f"(c[1]), "+f"(c[2]), "+f"(c[3])
        : "r"(a[0]), "r"(a[1]), "r"(a[2]), "r"(a[3]), "r"(b0), "r"(b1));
}

// =====================================================================
// Recurrent LSTM: cluster of 8 CTAs, W_hh in registers (unchanged).
// =====================================================================
template<int LAYER>
__global__ void __launch_bounds__(256, 1) __cluster_dims__(8, 1, 1)
lstm_rec(const float* __restrict__ x, const int* __restrict__ lengths,
         const float* __restrict__ Wih, const float* __restrict__ Whh,
         const float* __restrict__ bih, const float* __restrict__ bhh)
{
    __shared__ __align__(16) float hbuf[8 * 256];
    __shared__ __align__(16) float slice[2 * 8 * 32];
    __shared__ __align__(16) float part[8 * 8 * 32 * 4];

    cg::cluster_group cluster = cg::this_cluster();
    const int tid   = threadIdx.x;
    const int warp  = tid >> 5;
    const int lane  = tid & 31;
    const int crank = blockIdx.x & 7;
    const int group = blockIdx.x >> 3;
    const int dir   = group >> 3;
    const int bg    = group & 7;
    const int uglob = crank * 32 + lane;
    const int bglob = bg * 8 + warp;
    const int L     = lengths[bglob];

    float wreg[4][32];
    #pragma unroll
    for (int g = 0; g < 4; g++) {
        const float* wp = Whh + ((size_t)(dir * 1024 + g * 256 + uglob)) * 256 + warp * 32;
        #pragma unroll
        for (int q = 0; q < 8; q++) {
            float4 v = *reinterpret_cast<const float4*>(wp + q * 4);
            wreg[g][q * 4 + 0] = v.x; wreg[g][q * 4 + 1] = v.y;
            wreg[g][q * 4 + 2] = v.z; wreg[g][q * 4 + 3] = v.w;
        }
    }

    float wia[4], wib[4], wic[4], bs4[4];
    if (LAYER == 0) {
        #pragma unroll
        for (int g = 0; g < 4; g++) {
            int row = dir * 1024 + g * 256 + uglob;
            wia[g] = Wih[(size_t)row * 3 + 0];
            wib[g] = Wih[(size_t)row * 3 + 1];
            wic[g] = Wih[(size_t)row * 3 + 2];
            bs4[g] = bih[row] + bhh[row];
        }
    }

    for (int i = tid; i < 8 * 256; i += 256) hbuf[i] = 0.0f;
    __syncthreads();

    const int xb = tid >> 5;
    const int xi = tid & 31;
    const int xc = xi >> 2;
    const int xq = xi & 3;

    float c = 0.0f, h = 0.0f;

    for (int t = 0; t < T_SEQ; t++) {
        const bool m = (t < L);

        float p0, p1, p2, p3;
        if (LAYER == 0) {
            int teff = (dir == 0) ? t : (m ? (L - 1 - t) : t);
            const float* xp = x + ((size_t)bglob * T_SEQ + teff) * 3;
            float x0 = xp[0], x1 = xp[1], x2 = xp[2];
            p0 = bs4[0] + wia[0] * x0 + wib[0] * x1 + wic[0] * x2;
            p1 = bs4[1] + wia[1] * x0 + wib[1] * x1 + wic[1] * x2;
            p2 = bs4[2] + wia[2] * x0 + wib[2] * x1 + wic[2] * x2;
            p3 = bs4[3] + wia[3] * x0 + wib[3] * x1 + wic[3] * x2;
        } else {
            const float* gp = g_gx + (((size_t)dir * T_SEQ + t) * NB + bglob) * 1024 + uglob;
            p0 = __ldg(gp);       p1 = __ldg(gp + 256);
            p2 = __ldg(gp + 512); p3 = __ldg(gp + 768);
        }

        #pragma unroll
        for (int b = 0; b < 8; b++) {
            float a0 = 0.f, a1 = 0.f, a2 = 0.f, a3 = 0.f;
            const float* hb = hbuf + b * 256 + warp * 32;
            #pragma unroll
            for (int q = 0; q < 8; q++) {
                float4 hv = *reinterpret_cast<const float4*>(hb + q * 4);
                a0 = fmaf(wreg[0][q * 4 + 0], hv.x, a0);
                a0 = fmaf(wreg[0][q * 4 + 1], hv.y, a0);
                a0 = fmaf(wreg[0][q * 4 + 2], hv.z, a0);
                a0 = fmaf(wreg[0][q * 4 + 3], hv.w, a0);
                a1 = fmaf(wreg[1][q * 4 + 0], hv.x, a1);
                a1 = fmaf(wreg[1][q * 4 + 1], hv.y, a1);
                a1 = fmaf(wreg[1][q * 4 + 2], hv.z, a1);
                a1 = fmaf(wreg[1][q * 4 + 3], hv.w, a1);
                a2 = fmaf(wreg[2][q * 4 + 0], hv.x, a2);
                a2 = fmaf(wreg[2][q * 4 + 1], hv.y, a2);
                a2 = fmaf(wreg[2][q * 4 + 2], hv.z, a2);
                a2 = fmaf(wreg[2][q * 4 + 3], hv.w, a2);
                a3 = fmaf(wreg[3][q * 4 + 0], hv.x, a3);
                a3 = fmaf(wreg[3][q * 4 + 1], hv.y, a3);
                a3 = fmaf(wreg[3][q * 4 + 2], hv.z, a3);
                a3 = fmaf(wreg[3][q * 4 + 3], hv.w, a3);
            }
            *reinterpret_cast<float4*>(&part[((warp * 8 + b) * 32 + lane) * 4]) =
                make_float4(a0, a1, a2, a3);
        }
        __syncthreads();

        float g0 = p0, g1 = p1, g2 = p2, g3 = p3;
        #pragma unroll
        for (int w2 = 0; w2 < 8; w2++) {
            float4 v = *reinterpret_cast<const float4*>(&part[((w2 * 8 + warp) * 32 + lane) * 4]);
            g0 += v.x; g1 += v.y; g2 += v.z; g3 += v.w;
        }
        float ig = sigf(g0), fg = sigf(g1);
        float gg = tanhf(g2), og = sigf(g3);
        float cn = fmaf(fg, c, ig * gg);
        float hn = og * tanhf(cn);
        if (m) { c = cn; h = hn; }

        if (LAYER == 0) {
            int pos = (dir == 0) ? t : (m ? (L - 1 - t) : t);
            float val = m ? h : 0.0f;
            __nv_bfloat16 hi = __float2bfloat16(val);
            __nv_bfloat16 lo = __float2bfloat16(val - __bfloat162float(hi));
            size_t idx = ((size_t)bglob * T_SEQ + pos) * 512 + dir * 256 + uglob;
            g_h1h[idx] = hi;
            g_h1l[idx] = lo;
        } else if (dir == 1 && t == 0) {
            g_feat[bglob * 512 + 256 + uglob] = h;
        }

        const int p = t & 1;
        slice[p * 256 + warp * 32 + lane] = h;
        cluster.sync();
        {
            float* psl = cluster.map_shared_rank((float*)slice, (unsigned)xc);
            const float* src = psl + p * 256 + xb * 32 + xq * 4;
            float4 v0 = *reinterpret_cast<const float4*>(src);
            float4 v1 = *reinterpret_cast<const float4*>(src + 16);
            *reinterpret_cast<float4*>(hbuf + xb * 256 + xc * 32 + xq * 4)      = v0;
            *reinterpret_cast<float4*>(hbuf + xb * 256 + xc * 32 + xq * 4 + 16) = v1;
        }
        __syncthreads();
    }

    if (LAYER == 1 && dir == 0)
        g_feat[bglob * 512 + uglob] = h;
}

// =====================================================================
// W_ih_l1 fp32 -> bf16 hi/lo split
// =====================================================================
__global__ void __launch_bounds__(256) conv_w1(const float* __restrict__ Wih)
{
    size_t i = (size_t)blockIdx.x * 1024 + threadIdx.x * 4;
    float4 v = *reinterpret_cast<const float4*>(Wih + i);
    float vv[4] = {v.x, v.y, v.z, v.w};
    #pragma unroll
    for (int k = 0; k < 4; k++) {
        __nv_bfloat16 hi = __float2bfloat16(vv[k]);
        __nv_bfloat16 lo = __float2bfloat16(vv[k] - __bfloat162float(hi));
        g_w1h[i + k] = hi;
        g_w1l[i + k] = lo;
    }
}

// =====================================================================
// Layer-1 input projection via HMMA (mma.sync bf16, split hi/lo, 3 passes).
// CTA tile: M=64 (batch), N=128, K=512 in 16 chunks of 32.
// 8 warps in 2(m) x 4(n); warp tile 32x32.
// SMEM u32 tiles padded to stride 20 (conflict-free fragment loads).
// =====================================================================
__global__ void __launch_bounds__(256) gx_mma(
    const int* __restrict__ lengths,
    const float* __restrict__ bih, const float* __restrict__ bhh)
{
    __shared__ __align__(16) uint32_t Ah[64 * 20], Al[64 * 20];
    __shared__ __align__(16) uint32_t Bh[128 * 20], Bl[128 * 20];
    __shared__ float bias_s[128];

    const int tid  = threadIdx.x;
    const int wid  = tid >> 5;
    const int lane = tid & 31;
    const int g    = lane >> 2;
    const int t4   = lane & 3;
    const int n0   = blockIdx.x * 128;
    const int t    = blockIdx.y;
    const int dir  = blockIdx.z;

    const int m0 = (wid & 1) * 32;
    const int nw = (wid >> 1) * 32;

    // ---- loader assignments
    const int ar = tid >> 2, ac = tid & 3;       // A: row ar, quad ac (16 bf16)
    const int br = tid >> 1, bc = tid & 1;       // B: row br, half bc (32 bf16)
    {
        int La = lengths[ar];
        // teff computed once; bias into smem
        if (tid < 128) bias_s[tid] = bih[dir * 1024 + n0 + tid] + bhh[dir * 1024 + n0 + tid];
    }
    const int La = lengths[ar];
    const int teff = dir ? ((t < La) ? (La - 1 - t) : t) : t;
    const uint4* a_h = (const uint4*)(g_h1h + ((size_t)ar * T_SEQ + teff) * 512) + ac;
    const uint4* a_l = (const uint4*)(g_h1l + ((size_t)ar * T_SEQ + teff) * 512) + ac;
    const uint4* b_h = (const uint4*)(g_w1h + ((size_t)(dir * 1024 + n0 + br)) * 512) + bc * 2;
    const uint4* b_l = (const uint4*)(g_w1l + ((size_t)(dir * 1024 + n0 + br)) * 512) + bc * 2;

    float acc[2][4][4];
    #pragma unroll
    for (int i = 0; i < 2; i++)
        #pragma unroll
        for (int j = 0; j < 4; j++)
            #pragma unroll
            for (int k = 0; k < 4; k++) acc[i][j][k] = 0.0f;

    // prefetch chunk 0
    uint4 vah = __ldg(a_h), val_ = __ldg(a_l);
    uint4 vbh0 = __ldg(b_h), vbh1 = __ldg(b_h + 1);
    uint4 vbl0 = __ldg(b_l), vbl1 = __ldg(b_l + 1);

    for (int kc = 0; kc < 16; kc++) {
        // store current chunk to SMEM
        *reinterpret_cast<uint4*>(&Ah[ar * 20 + ac * 4]) = vah;
        *reinterpret_cast<uint4*>(&Al[ar * 20 + ac * 4]) = val_;
        *reinterpret_cast<uint4*>(&Bh[br * 20 + bc * 8])     = vbh0;
        *reinterpret_cast<uint4*>(&Bh[br * 20 + bc * 8 + 4]) = vbh1;
        *reinterpret_cast<uint4*>(&Bl[br * 20 + bc * 8])     = vbl0;
        *reinterpret_cast<uint4*>(&Bl[br * 20 + bc * 8 + 4]) = vbl1;
        __syncthreads();

        if (kc + 1 < 16) {   // prefetch next chunk (overlaps with MMA)
            vah  = __ldg(a_h + (kc + 1) * 4);
            val_ = __ldg(a_l + (kc + 1) * 4);
            vbh0 = __ldg(b_h + (kc + 1) * 4);
            vbh1 = __ldg(b_h + (kc + 1) * 4 + 1);
            vbl0 = __ldg(b_l + (kc + 1) * 4);
            vbl1 = __ldg(b_l + (kc + 1) * 4 + 1);
        }

        #pragma unroll
        for (int pass = 0; pass < 3; pass++) {
            const uint32_t* Am = (pass == 2) ? Al : Ah;
            const uint32_t* Bm = (pass == 1) ? Bl : Bh;
            #pragma unroll
            for (int ks = 0; ks < 2; ks++) {
                uint32_t a[2][4];
                #pragma unroll
                for (int mf = 0; mf < 2; mf++) {
                    int r = m0 + mf * 16 + g;
                    a[mf][0] = Am[r * 20 + ks * 8 + t4];
                    a[mf][1] = Am[(r + 8) * 20 + ks * 8 + t4];
                    a[mf][2] = Am[r * 20 + ks * 8 + t4 + 4];
                    a[mf][3] = Am[(r + 8) * 20 + ks * 8 + t4 + 4];
                }
                #pragma unroll
                for (int nf = 0; nf < 4; nf++) {
                    int rn = nw + nf * 8 + g;
                    uint32_t b0 = Bm[rn * 20 + ks * 8 + t4];
                    uint32_t b1 = Bm[rn * 20 + ks * 8 + t4 + 4];
                    mma_bf16(acc[0][nf], a[0], b0, b1);
                    mma_bf16(acc[1][nf], a[1], b0, b1);
                }
            }
        }
        __syncthreads();
    }

    // ---- epilogue: +bias, float2 stores
    float* gxp = g_gx + ((size_t)(dir * T_SEQ + t) * NB) * 1024 + n0;
    #pragma unroll
    for (int mf = 0; mf < 2; mf++) {
        int bi = m0 + mf * 16 + g;
        #pragma unroll
        for (int nf = 0; nf < 4; nf++) {
            int nn = nw + nf * 8 + t4 * 2;
            float bv0 = bias_s[nn], bv1 = bias_s[nn + 1];
            float2 v0 = make_float2(acc[mf][nf][0] + bv0, acc[mf][nf][1] + bv1);
            float2 v1 = make_float2(acc[mf][nf][2] + bv0, acc[mf][nf][3] + bv1);
            *reinterpret_cast<float2*>(gxp + (size_t)bi * 1024 + nn)       = v0;
            *reinterpret_cast<float2*>(gxp + (size_t)(bi + 8) * 1024 + nn) = v1;
        }
    }
}

// =====================================================================
// Head
// =====================================================================
__global__ void __launch_bounds__(256) head_fc1(const float* __restrict__ fc1_w,
                                                const float* __restrict__ fc1_b)
{
    __shared__ __align__(16) float fs[512];
    int b = blockIdx.x, n = threadIdx.x;
    for (int i = n; i < 512; i += 256) fs[i] = g_feat[b * 512 + i];
    __syncthreads();
    const float4* wp = reinterpret_cast<const float4*>(fc1_w + (size_t)n * 512);
    const float4* fp = reinterpret_cast<const float4*>(fs);
    float acc = fc1_b[n];
    #pragma unroll 4
    for (int k = 0; k < 128; k++) {
        float4 w4 = __ldg(wp + k);
        float4 f4 = fp[k];
        acc += w4.x * f4.x + w4.y * f4.y + w4.z * f4.z + w4.w * f4.w;
    }
    g_y[b * 256 + n] = fmaxf(acc, 0.0f);
}

__global__ void head_bn(const float* __restrict__ gamma, const float* __restrict__ beta)
{
    int n = threadIdx.x;
    float s = 0.0f, s2 = 0.0f;
    for (int b = 0; b < 64; b++) {
        float v = g_y[b * 256 + n];
        s += v; s2 += v * v;
    }
    float mean = s * 0.015625f;
    float var  = s2 * 0.015625f - mean * mean;
    float inv  = rsqrtf(var + 1e-5f);
    float ga = gamma[n] * inv, be = beta[n];
    for (int b = 0; b < 64; b++)
        g_y[b * 256 + n] = (g_y[b * 256 + n] - mean) * ga + be;
}

__global__ void __launch_bounds__(256) head_out(const float* __restrict__ W,
                                                const float* __restrict__ bias,
                                                float* __restrict__ out)
{
    __shared__ __align__(16) float ys[256];
    int b = blockIdx.x;
    ys[threadIdx.x] = g_y[b * 256 + threadIdx.x];
    __syncthreads();
    int o = threadIdx.x;
    if (o < 196) {
        const float4* wp = reinterpret_cast<const float4*>(W + (size_t)o * 256);
        const float4* yp = reinterpret_cast<const float4*>(ys);
        float acc = bias[o];
        #pragma unroll 4
        for (int k = 0; k < 64; k++) {
            float4 w4 = __ldg(wp + k);
            float4 y4 = yp[k];
            acc += w4.x * y4.x + w4.y * y4.y + w4.z * y4.z + w4.w * y4.w;
        }
        out[(size_t)b * 196 + o] = acc;
    }
}

// =====================================================================
extern "C" void kernel_launch(void* const* d_in, const int* in_sizes, int n_in,
                              void* d_out, int out_size)
{
    const float* x       = (const float*)d_in[0];
    const int*   lengths = (const int*)  d_in[1];
    const float* Wih0    = (const float*)d_in[2];
    const float* Whh0    = (const float*)d_in[3];
    const float* bih0    = (const float*)d_in[4];
    const float* bhh0    = (const float*)d_in[5];
    const float* Wih1    = (const float*)d_in[6];
    const float* Whh1    = (const float*)d_in[7];
    const float* bih1    = (const float*)d_in[8];
    const float* bhh1    = (const float*)d_in[9];
    const float* fc1_w   = (const float*)d_in[10];
    const float* fc1_b   = (const float*)d_in[11];
    const float* gamma   = (const float*)d_in[12];
    const float* beta    = (const float*)d_in[13];
    const float* fcow    = (const float*)d_in[14];
    const float* fcob    = (const float*)d_in[15];
    float* out = (float*)d_out;

    conv_w1<<<1024, 256>>>(Wih1);
    lstm_rec<0><<<128, 256>>>(x, lengths, Wih0, Whh0, bih0, bhh0);
    gx_mma<<<dim3(8, 1024, 2), 256>>>(lengths, bih1, bhh1);
    lstm_rec<1><<<128, 256>>>(x, lengths, Wih1, Whh1, bih1, bhh1);
    head_fc1<<<64, 256>>>(fc1_w, fc1_b);
    head_bn<<<1, 256>>>(gamma, beta);
    head_out<<<64, 256>>>(fcow, fcob, out);
}

// round 5
// speedup vs baseline: 1.2706x; 1.1325x over previous
#include <cuda_runtime.h>
#include <cuda_bf16.h>
#include <cooperative_groups.h>
#include <cstdint>
#include <cstddef>

namespace cg = cooperative_groups;

#define HID   256
#define T_SEQ 1024
#define NB    64

// ---------------- scratch (device globals; no allocation) ----------------
__device__ __nv_bfloat16 g_h1h[(size_t)NB * T_SEQ * 512];   // layer-0 out, bf16 hi
__device__ __nv_bfloat16 g_h1l[(size_t)NB * T_SEQ * 512];   // layer-0 out, bf16 lo
__device__ __nv_bfloat16 g_w1h[(size_t)2 * 1024 * 512];     // W_ih_l1 bf16 hi
__device__ __nv_bfloat16 g_w1l[(size_t)2 * 1024 * 512];     // W_ih_l1 bf16 lo
__device__ float g_gx[(size_t)2 * T_SEQ * NB * 1024];       // layer-1 projected gates
__device__ float g_feat[NB * 512];
__device__ float g_y[NB * 256];

__device__ __forceinline__ float sigf(float x) {
    return __fdividef(1.0f, 1.0f + __expf(-x));
}

// mma.sync m16n8k16 row.col bf16 -> f32 (validated fragment layout in gx_mma)
__device__ __forceinline__ void mma_bf16(float* c, const uint32_t* a,
                                         uint32_t b0, uint32_t b1) {
    asm volatile(
        "mma.sync.aligned.m16n8k16.row.col.f32.bf16.bf16.f32 "
        "{%0,%1,%2,%3}, {%4,%5,%6,%7}, {%8,%9}, {%0,%1,%2,%3};"
        : "+f"(c[0]), "+f"(c[1]), "+f"(c[2]), "+f"(c[3])
        : "r"(a[0]), "r"(a[1]), "r"(a[2]), "r"(a[3]), "r"(b0), "r"(b1));
}

__device__ __forceinline__ uint32_t pack_bf16(float a, float b) {
    __nv_bfloat162 v = __floats2bfloat162_rn(a, b);   // .x = a (low), .y = b (high)
    return *reinterpret_cast<uint32_t*>(&v);
}
__device__ __forceinline__ float bf_res(float x) {
    return x - __bfloat162float(__float2bfloat16(x));
}

// =====================================================================
// Recurrent LSTM on tensor cores.
// Cluster of 8 CTAs = (dir, batch-group-of-8). CTA = 256 thr (8 warps).
// Per CTA: gate-rows r_local = gate*32 + u_local (128 rows), warp w owns
// rows [w*16, w*16+16). W_hh fragments (split bf16 hi/lo) live in REGISTERS.
// Per step: h(t-1) bf16 hi/lo in SMEM A-tiles -> 96 HMMA/warp -> dump gates
// -> per-thread (b,u) nonlinearity -> publish slice -> cluster.sync ->
// DSMEM gather -> fp32->bf16 convert into A-tiles.
// =====================================================================
template<int LAYER>
__global__ void __launch_bounds__(256, 1) __cluster_dims__(8, 1, 1)
lstm_rec(const float* __restrict__ x, const int* __restrict__ lengths,
         const float* __restrict__ Wih, const float* __restrict__ Whh,
         const float* __restrict__ bih, const float* __restrict__ bhh)
{
    __shared__ __align__(16) uint32_t Ah[16 * 132];     // A hi [row][kpair], rows 8..15 zero
    __shared__ __align__(16) uint32_t Al[16 * 132];     // A lo
    __shared__ __align__(16) float hbuf[8 * 256];       // gathered fp32 h
    __shared__ __align__(16) float slice[2 * 8 * 32];   // double-buffered own slice
    __shared__ __align__(16) float gates_s[8 * 132];    // [b][r_local]

    cg::cluster_group cluster = cg::this_cluster();
    const int tid   = threadIdx.x;
    const int w     = tid >> 5;
    const int lane  = tid & 31;
    const int g     = lane >> 2;
    const int t4    = lane & 3;
    const int crank = blockIdx.x & 7;
    const int group = blockIdx.x >> 3;
    const int dir   = group >> 3;
    const int bg    = group & 7;
    const int b_upd = tid >> 5;              // update-thread batch
    const int u     = lane;                  // update-thread unit (local)
    const int uglob = crank * 32 + u;
    const int bglob = bg * 8 + b_upd;
    const int L     = lengths[bglob];

    // ---- W_hh fragments into registers: bfh/bfl[ks][j][slot]
    uint32_t bfh[16][2][2], bfl[16][2][2];
    #pragma unroll
    for (int j = 0; j < 2; j++) {
        int rl   = w * 16 + j * 8 + g;
        int grow = dir * 1024 + ((rl >> 5) << 8) + crank * 32 + (rl & 31);
        const float* wp = Whh + (size_t)grow * 256;
        #pragma unroll
        for (int ks = 0; ks < 16; ks++) {
            #pragma unroll
            for (int s = 0; s < 2; s++) {
                int kp = ks * 8 + t4 + s * 4;
                float2 wv = *reinterpret_cast<const float2*>(wp + kp * 2);
                bfh[ks][j][s] = pack_bf16(wv.x, wv.y);
                bfl[ks][j][s] = pack_bf16(bf_res(wv.x), bf_res(wv.y));
            }
        }
    }

    // ---- layer-0 input projection params (IN = 3) for update thread
    float wia[4], wib[4], wic[4], bs4[4];
    if (LAYER == 0) {
        #pragma unroll
        for (int q = 0; q < 4; q++) {
            int row = dir * 1024 + q * 256 + uglob;
            wia[q] = Wih[(size_t)row * 3 + 0];
            wib[q] = Wih[(size_t)row * 3 + 1];
            wic[q] = Wih[(size_t)row * 3 + 2];
            bs4[q] = bih[row] + bhh[row];
        }
    }

    for (int i = tid; i < 16 * 132; i += 256) { Ah[i] = 0u; Al[i] = 0u; }
    for (int i = tid; i < 8 * 256; i += 256) hbuf[i] = 0.0f;
    __syncthreads();

    // DSMEM gather mapping (unchanged, validated)
    const int xb = tid >> 5;
    const int xi = tid & 31;
    const int xc = xi >> 2;
    const int xq = xi & 3;

    float c = 0.0f, h = 0.0f;

    for (int t = 0; t < T_SEQ; t++) {
        const bool m = (t < L);

        // ---- input-projection preacts (issue loads early; MMA hides latency)
        float p0, p1, p2, p3;
        if (LAYER == 0) {
            int teff = (dir == 0) ? t : (m ? (L - 1 - t) : t);
            const float* xp = x + ((size_t)bglob * T_SEQ + teff) * 3;
            float x0 = xp[0], x1 = xp[1], x2 = xp[2];
            p0 = bs4[0] + wia[0] * x0 + wib[0] * x1 + wic[0] * x2;
            p1 = bs4[1] + wia[1] * x0 + wib[1] * x1 + wic[1] * x2;
            p2 = bs4[2] + wia[2] * x0 + wib[2] * x1 + wic[2] * x2;
            p3 = bs4[3] + wia[3] * x0 + wib[3] * x1 + wic[3] * x2;
        } else {
            const float* gp = g_gx + (((size_t)dir * T_SEQ + t) * NB + bglob) * 1024 + uglob;
            p0 = __ldg(gp);       p1 = __ldg(gp + 256);
            p2 = __ldg(gp + 512); p3 = __ldg(gp + 768);
        }

        // ---- recurrent matvec: 3-pass split-bf16 HMMA, warp tile 16x16
        float acc0[4] = {0.f, 0.f, 0.f, 0.f};
        float acc1[4] = {0.f, 0.f, 0.f, 0.f};
        #pragma unroll
        for (int ks = 0; ks < 16; ks++) {
            const int kp = ks * 8 + t4;
            uint32_t ah[4], al[4];
            ah[0] = Ah[g * 132 + kp];           ah[1] = Ah[(g + 8) * 132 + kp];
            ah[2] = Ah[g * 132 + kp + 4];       ah[3] = Ah[(g + 8) * 132 + kp + 4];
            al[0] = Al[g * 132 + kp];           al[1] = Al[(g + 8) * 132 + kp];
            al[2] = Al[g * 132 + kp + 4];       al[3] = Al[(g + 8) * 132 + kp + 4];
            mma_bf16(acc0, ah, bfh[ks][0][0], bfh[ks][0][1]);
            mma_bf16(acc0, ah, bfl[ks][0][0], bfl[ks][0][1]);
            mma_bf16(acc0, al, bfh[ks][0][0], bfh[ks][0][1]);
            mma_bf16(acc1, ah, bfh[ks][1][0], bfh[ks][1][1]);
            mma_bf16(acc1, ah, bfl[ks][1][0], bfl[ks][1][1]);
            mma_bf16(acc1, al, bfh[ks][1][0], bfh[ks][1][1]);
        }

        // ---- dump gates (row g = batch; cols = r_local); rows g+8 are padding
        *reinterpret_cast<float2*>(&gates_s[g * 132 + w * 16 + 2 * t4]) =
            make_float2(acc0[0], acc0[1]);
        *reinterpret_cast<float2*>(&gates_s[g * 132 + w * 16 + 8 + 2 * t4]) =
            make_float2(acc1[0], acc1[1]);
        __syncthreads();

        // ---- gate nonlinearity + state update: thread (b_upd, u)
        float g0 = p0 + gates_s[b_upd * 132 + u];
        float g1 = p1 + gates_s[b_upd * 132 + 32 + u];
        float g2 = p2 + gates_s[b_upd * 132 + 64 + u];
        float g3 = p3 + gates_s[b_upd * 132 + 96 + u];
        float ig = sigf(g0), fg = sigf(g1);
        float gg = tanhf(g2), og = sigf(g3);
        float cn = fmaf(fg, c, ig * gg);
        float hn = og * tanhf(cn);
        if (m) { c = cn; h = hn; }

        if (LAYER == 0) {
            int pos = (dir == 0) ? t : (m ? (L - 1 - t) : t);
            float val = m ? h : 0.0f;
            __nv_bfloat16 hi = __float2bfloat16(val);
            __nv_bfloat16 lo = __float2bfloat16(val - __bfloat162float(hi));
            size_t idx = ((size_t)bglob * T_SEQ + pos) * 512 + dir * 256 + uglob;
            g_h1h[idx] = hi;
            g_h1l[idx] = lo;
        } else if (dir == 1 && t == 0) {
            g_feat[bglob * 512 + 256 + uglob] = h;
        }

        // ---- publish slice, cluster-sync, gather full h
        const int p = t & 1;
        slice[p * 256 + b_upd * 32 + u] = h;
        cluster.sync();
        {
            float* psl = cluster.map_shared_rank((float*)slice, (unsigned)xc);
            const float* src = psl + p * 256 + xb * 32 + xq * 4;
            float4 v0 = *reinterpret_cast<const float4*>(src);
            float4 v1 = *reinterpret_cast<const float4*>(src + 16);
            *reinterpret_cast<float4*>(hbuf + xb * 256 + xc * 32 + xq * 4)      = v0;
            *reinterpret_cast<float4*>(hbuf + xb * 256 + xc * 32 + xq * 4 + 16) = v1;
        }
        __syncthreads();

        // ---- convert fp32 h -> bf16 hi/lo A tiles (rows 0..7)
        #pragma unroll
        for (int i = 0; i < 4; i++) {
            int pi = tid * 4 + i;
            int bb = pi >> 7, kp = pi & 127;
            float2 hv = *reinterpret_cast<const float2*>(&hbuf[bb * 256 + kp * 2]);
            Ah[bb * 132 + kp] = pack_bf16(hv.x, hv.y);
            Al[bb * 132 + kp] = pack_bf16(bf_res(hv.x), bf_res(hv.y));
        }
        __syncthreads();
    }

    if (LAYER == 1 && dir == 0)
        g_feat[bglob * 512 + uglob] = h;
}

// =====================================================================
// W_ih_l1 fp32 -> bf16 hi/lo split
// =====================================================================
__global__ void __launch_bounds__(256) conv_w1(const float* __restrict__ Wih)
{
    size_t i = (size_t)blockIdx.x * 1024 + threadIdx.x * 4;
    float4 v = *reinterpret_cast<const float4*>(Wih + i);
    float vv[4] = {v.x, v.y, v.z, v.w};
    #pragma unroll
    for (int k = 0; k < 4; k++) {
        __nv_bfloat16 hi = __float2bfloat16(vv[k]);
        __nv_bfloat16 lo = __float2bfloat16(vv[k] - __bfloat162float(hi));
        g_w1h[i + k] = hi;
        g_w1l[i + k] = lo;
    }
}

// =====================================================================
// Layer-1 input projection via HMMA (unchanged, validated).
// =====================================================================
__global__ void __launch_bounds__(256) gx_mma(
    const int* __restrict__ lengths,
    const float* __restrict__ bih, const float* __restrict__ bhh)
{
    __shared__ __align__(16) uint32_t Ah[64 * 20], Al[64 * 20];
    __shared__ __align__(16) uint32_t Bh[128 * 20], Bl[128 * 20];
    __shared__ float bias_s[128];

    const int tid  = threadIdx.x;
    const int wid  = tid >> 5;
    const int lane = tid & 31;
    const int g    = lane >> 2;
    const int t4   = lane & 3;
    const int n0   = blockIdx.x * 128;
    const int t    = blockIdx.y;
    const int dir  = blockIdx.z;

    const int m0 = (wid & 1) * 32;
    const int nw = (wid >> 1) * 32;

    const int ar = tid >> 2, ac = tid & 3;
    const int br = tid >> 1, bc = tid & 1;
    if (tid < 128) bias_s[tid] = bih[dir * 1024 + n0 + tid] + bhh[dir * 1024 + n0 + tid];

    const int La = lengths[ar];
    const int teff = dir ? ((t < La) ? (La - 1 - t) : t) : t;
    const uint4* a_h = (const uint4*)(g_h1h + ((size_t)ar * T_SEQ + teff) * 512) + ac;
    const uint4* a_l = (const uint4*)(g_h1l + ((size_t)ar * T_SEQ + teff) * 512) + ac;
    const uint4* b_h = (const uint4*)(g_w1h + ((size_t)(dir * 1024 + n0 + br)) * 512) + bc * 2;
    const uint4* b_l = (const uint4*)(g_w1l + ((size_t)(dir * 1024 + n0 + br)) * 512) + bc * 2;

    float acc[2][4][4];
    #pragma unroll
    for (int i = 0; i < 2; i++)
        #pragma unroll
        for (int j = 0; j < 4; j++)
            #pragma unroll
            for (int k = 0; k < 4; k++) acc[i][j][k] = 0.0f;

    uint4 vah = __ldg(a_h), val_ = __ldg(a_l);
    uint4 vbh0 = __ldg(b_h), vbh1 = __ldg(b_h + 1);
    uint4 vbl0 = __ldg(b_l), vbl1 = __ldg(b_l + 1);

    for (int kc = 0; kc < 16; kc++) {
        *reinterpret_cast<uint4*>(&Ah[ar * 20 + ac * 4]) = vah;
        *reinterpret_cast<uint4*>(&Al[ar * 20 + ac * 4]) = val_;
        *reinterpret_cast<uint4*>(&Bh[br * 20 + bc * 8])     = vbh0;
        *reinterpret_cast<uint4*>(&Bh[br * 20 + bc * 8 + 4]) = vbh1;
        *reinterpret_cast<uint4*>(&Bl[br * 20 + bc * 8])     = vbl0;
        *reinterpret_cast<uint4*>(&Bl[br * 20 + bc * 8 + 4]) = vbl1;
        __syncthreads();

        if (kc + 1 < 16) {
            vah  = __ldg(a_h + (kc + 1) * 4);
            val_ = __ldg(a_l + (kc + 1) * 4);
            vbh0 = __ldg(b_h + (kc + 1) * 4);
            vbh1 = __ldg(b_h + (kc + 1) * 4 + 1);
            vbl0 = __ldg(b_l + (kc + 1) * 4);
            vbl1 = __ldg(b_l + (kc + 1) * 4 + 1);
        }

        #pragma unroll
        for (int pass = 0; pass < 3; pass++) {
            const uint32_t* Am = (pass == 2) ? Al : Ah;
            const uint32_t* Bm = (pass == 1) ? Bl : Bh;
            #pragma unroll
            for (int ks = 0; ks < 2; ks++) {
                uint32_t a[2][4];
                #pragma unroll
                for (int mf = 0; mf < 2; mf++) {
                    int r = m0 + mf * 16 + g;
                    a[mf][0] = Am[r * 20 + ks * 8 + t4];
                    a[mf][1] = Am[(r + 8) * 20 + ks * 8 + t4];
                    a[mf][2] = Am[r * 20 + ks * 8 + t4 + 4];
                    a[mf][3] = Am[(r + 8) * 20 + ks * 8 + t4 + 4];
                }
                #pragma unroll
                for (int nf = 0; nf < 4; nf++) {
                    int rn = nw + nf * 8 + g;
                    uint32_t b0 = Bm[rn * 20 + ks * 8 + t4];
                    uint32_t b1 = Bm[rn * 20 + ks * 8 + t4 + 4];
                    mma_bf16(acc[0][nf], a[0], b0, b1);
                    mma_bf16(acc[1][nf], a[1], b0, b1);
                }
            }
        }
        __syncthreads();
    }

    float* gxp = g_gx + ((size_t)(dir * T_SEQ + t) * NB) * 1024 + n0;
    #pragma unroll
    for (int mf = 0; mf < 2; mf++) {
        int bi = m0 + mf * 16 + g;
        #pragma unroll
        for (int nf = 0; nf < 4; nf++) {
            int nn = nw + nf * 8 + t4 * 2;
            float bv0 = bias_s[nn], bv1 = bias_s[nn + 1];
            float2 v0 = make_float2(acc[mf][nf][0] + bv0, acc[mf][nf][1] + bv1);
            float2 v1 = make_float2(acc[mf][nf][2] + bv0, acc[mf][nf][3] + bv1);
            *reinterpret_cast<float2*>(gxp + (size_t)bi * 1024 + nn)       = v0;
            *reinterpret_cast<float2*>(gxp + (size_t)(bi + 8) * 1024 + nn) = v1;
        }
    }
}

// =====================================================================
// Head
// =====================================================================
__global__ void __launch_bounds__(256) head_fc1(const float* __restrict__ fc1_w,
                                                const float* __restrict__ fc1_b)
{
    __shared__ __align__(16) float fs[512];
    int b = blockIdx.x, n = threadIdx.x;
    for (int i = n; i < 512; i += 256) fs[i] = g_feat[b * 512 + i];
    __syncthreads();
    const float4* wp = reinterpret_cast<const float4*>(fc1_w + (size_t)n * 512);
    const float4* fp = reinterpret_cast<const float4*>(fs);
    float acc = fc1_b[n];
    #pragma unroll 4
    for (int k = 0; k < 128; k++) {
        float4 w4 = __ldg(wp + k);
        float4 f4 = fp[k];
        acc += w4.x * f4.x + w4.y * f4.y + w4.z * f4.z + w4.w * f4.w;
    }
    g_y[b * 256 + n] = fmaxf(acc, 0.0f);
}

__global__ void head_bn(const float* __restrict__ gamma, const float* __restrict__ beta)
{
    int n = threadIdx.x;
    float s = 0.0f, s2 = 0.0f;
    for (int b = 0; b < 64; b++) {
        float v = g_y[b * 256 + n];
        s += v; s2 += v * v;
    }
    float mean = s * 0.015625f;
    float var  = s2 * 0.015625f - mean * mean;
    float inv  = rsqrtf(var + 1e-5f);
    float ga = gamma[n] * inv, be = beta[n];
    for (int b = 0; b < 64; b++)
        g_y[b * 256 + n] = (g_y[b * 256 + n] - mean) * ga + be;
}

__global__ void __launch_bounds__(256) head_out(const float* __restrict__ W,
                                                const float* __restrict__ bias,
                                                float* __restrict__ out)
{
    __shared__ __align__(16) float ys[256];
    int b = blockIdx.x;
    ys[threadIdx.x] = g_y[b * 256 + threadIdx.x];
    __syncthreads();
    int o = threadIdx.x;
    if (o < 196) {
        const float4* wp = reinterpret_cast<const float4*>(W + (size_t)o * 256);
        const float4* yp = reinterpret_cast<const float4*>(ys);
        float acc = bias[o];
        #pragma unroll 4
        for (int k = 0; k < 64; k++) {
            float4 w4 = __ldg(wp + k);
            float4 y4 = yp[k];
            acc += w4.x * y4.x + w4.y * y4.y + w4.z * y4.z + w4.w * y4.w;
        }
        out[(size_t)b * 196 + o] = acc;
    }
}

// =====================================================================
extern "C" void kernel_launch(void* const* d_in, const int* in_sizes, int n_in,
                              void* d_out, int out_size)
{
    const float* x       = (const float*)d_in[0];
    const int*   lengths = (const int*)  d_in[1];
    const float* Wih0    = (const float*)d_in[2];
    const float* Whh0    = (const float*)d_in[3];
    const float* bih0    = (const float*)d_in[4];
    const float* bhh0    = (const float*)d_in[5];
    const float* Wih1    = (const float*)d_in[6];
    const float* Whh1    = (const float*)d_in[7];
    const float* bih1    = (const float*)d_in[8];
    const float* bhh1    = (const float*)d_in[9];
    const float* fc1_w   = (const float*)d_in[10];
    const float* fc1_b   = (const float*)d_in[11];
    const float* gamma   = (const float*)d_in[12];
    const float* beta    = (const float*)d_in[13];
    const float* fcow    = (const float*)d_in[14];
    const float* fcob    = (const float*)d_in[15];
    float* out = (float*)d_out;

    conv_w1<<<1024, 256>>>(Wih1);
    lstm_rec<0><<<128, 256>>>(x, lengths, Wih0, Whh0, bih0, bhh0);
    gx_mma<<<dim3(8, 1024, 2), 256>>>(lengths, bih1, bhh1);
    lstm_rec<1><<<128, 256>>>(x, lengths, Wih1, Whh1, bih1, bhh1);
    head_fc1<<<64, 256>>>(fc1_w, fc1_b);
    head_bn<<<1, 256>>>(gamma, beta);
    head_out<<<64, 256>>>(fcow, fcob, out);
}

// round 6
// speedup vs baseline: 1.3183x; 1.0376x over previous
#include <cuda_runtime.h>
#include <cuda_bf16.h>
#include <cooperative_groups.h>
#include <cstdint>
#include <cstddef>

namespace cg = cooperative_groups;

#define HID   256
#define T_SEQ 1024
#define NB    64

// ---------------- scratch (device globals; no allocation) ----------------
__device__ __nv_bfloat16 g_h1h[(size_t)NB * T_SEQ * 512];   // layer-0 out, bf16 hi
__device__ __nv_bfloat16 g_h1l[(size_t)NB * T_SEQ * 512];   // layer-0 out, bf16 lo
__device__ __nv_bfloat16 g_w1h[(size_t)2 * 1024 * 512];     // W_ih_l1 bf16 hi
__device__ __nv_bfloat16 g_w1l[(size_t)2 * 1024 * 512];     // W_ih_l1 bf16 lo
__device__ float g_gx[(size_t)2 * T_SEQ * NB * 1024];       // layer-1 projected gates
__device__ float g_feat[NB * 512];
__device__ float g_y[NB * 256];

__device__ __forceinline__ float sigf(float x) {
    return __fdividef(1.0f, 1.0f + __expf(-x));
}

// mma.sync m16n8k16 row.col bf16 -> f32 (validated fragment layout)
__device__ __forceinline__ void mma_bf16(float* c, const uint32_t* a,
                                         uint32_t b0, uint32_t b1) {
    asm volatile(
        "mma.sync.aligned.m16n8k16.row.col.f32.bf16.bf16.f32 "
        "{%0,%1,%2,%3}, {%4,%5,%6,%7}, {%8,%9}, {%0,%1,%2,%3};"
        : "+f"(c[0]), "+f"(c[1]), "+f"(c[2]), "+f"(c[3])
        : "r"(a[0]), "r"(a[1]), "r"(a[2]), "r"(a[3]), "r"(b0), "r"(b1));
}

// ldmatrix x4: canonical A-operand load for m16n8k16 (row-major 16x16 bf16)
__device__ __forceinline__ void ldsm4(uint32_t* r, uint32_t addr) {
    asm volatile(
        "ldmatrix.sync.aligned.m8n8.x4.shared.b16 {%0,%1,%2,%3}, [%4];"
        : "=r"(r[0]), "=r"(r[1]), "=r"(r[2]), "=r"(r[3]) : "r"(addr));
}

__device__ __forceinline__ uint32_t smem_u32(const void* p) {
    uint32_t a;
    asm("{ .reg .u64 t; cvta.to.shared.u64 t, %1; cvt.u32.u64 %0, t; }" : "=r"(a) : "l"(p));
    return a;
}

__device__ __forceinline__ uint32_t pack_bf16(float a, float b) {
    __nv_bfloat162 v = __floats2bfloat162_rn(a, b);
    return *reinterpret_cast<uint32_t*>(&v);
}
__device__ __forceinline__ float bf_res(float x) {
    return x - __bfloat162float(__float2bfloat16(x));
}

// =====================================================================
// Recurrent LSTM on tensor cores. Cluster of 8 CTAs = (dir, batch-group).
// W_hh split-bf16 fragments in registers. Per step:
//   ldmatrix A (hi/lo) -> 96 HMMA into 6 independent acc chains -> sum ->
//   gates dump -> update -> publish slice -> cluster arrive / (h1 store) /
//   wait -> DSMEM gather fused with fp32->bf16 hi/lo convert into A tiles.
// =====================================================================
template<int LAYER>
__global__ void __launch_bounds__(256, 1) __cluster_dims__(8, 1, 1)
lstm_rec(const float* __restrict__ x, const int* __restrict__ lengths,
         const float* __restrict__ Wih, const float* __restrict__ Whh,
         const float* __restrict__ bih, const float* __restrict__ bhh)
{
    __shared__ __align__(16) uint32_t Ah[16 * 132];     // A hi, rows 8..15 stay zero
    __shared__ __align__(16) uint32_t Al[16 * 132];     // A lo
    __shared__ __align__(16) float slice[2 * 8 * 32];   // double-buffered own h slice
    __shared__ __align__(16) float gates_s[8 * 132];    // [b][r_local]

    cg::cluster_group cluster = cg::this_cluster();
    const int tid   = threadIdx.x;
    const int w     = tid >> 5;
    const int lane  = tid & 31;
    const int g     = lane >> 2;
    const int t4    = lane & 3;
    const int crank = blockIdx.x & 7;
    const int group = blockIdx.x >> 3;
    const int dir   = group >> 3;
    const int bg    = group & 7;
    const int b_upd = w;                     // update-thread batch
    const int u     = lane;                  // update-thread unit (local)
    const int uglob = crank * 32 + u;
    const int bglob = bg * 8 + b_upd;
    const int L     = lengths[bglob];

    // ---- W_hh fragments into registers: bfh/bfl[ks][j][slot]
    uint32_t bfh[16][2][2], bfl[16][2][2];
    #pragma unroll
    for (int j = 0; j < 2; j++) {
        int rl   = w * 16 + j * 8 + g;
        int grow = dir * 1024 + ((rl >> 5) << 8) + crank * 32 + (rl & 31);
        const float* wp = Whh + (size_t)grow * 256;
        #pragma unroll
        for (int ks = 0; ks < 16; ks++) {
            #pragma unroll
            for (int s = 0; s < 2; s++) {
                int kp = ks * 8 + t4 + s * 4;
                float2 wv = *reinterpret_cast<const float2*>(wp + kp * 2);
                bfh[ks][j][s] = pack_bf16(wv.x, wv.y);
                bfl[ks][j][s] = pack_bf16(bf_res(wv.x), bf_res(wv.y));
            }
        }
    }

    // ---- layer-0 input projection params (IN = 3) for update thread
    float wia[4], wib[4], wic[4], bs4[4];
    if (LAYER == 0) {
        #pragma unroll
        for (int q = 0; q < 4; q++) {
            int row = dir * 1024 + q * 256 + uglob;
            wia[q] = Wih[(size_t)row * 3 + 0];
            wib[q] = Wih[(size_t)row * 3 + 1];
            wic[q] = Wih[(size_t)row * 3 + 2];
            bs4[q] = bih[row] + bhh[row];
        }
    }

    for (int i = tid; i < 16 * 132; i += 256) { Ah[i] = 0u; Al[i] = 0u; }
    __syncthreads();

    // ldmatrix per-lane base addresses (row = lane&15, +4 kpairs for lanes>=16)
    const int lrow  = lane & 15;
    const int lcoff = (lane >> 4) * 4;
    const uint32_t aBaseH = smem_u32(Ah) + (uint32_t)(lrow * 132 + lcoff) * 4u;
    const uint32_t aBaseL = smem_u32(Al) + (uint32_t)(lrow * 132 + lcoff) * 4u;

    // DSMEM gather mapping: thread -> (batch xb, peer xc, unit-octet xq)
    const int xb = tid >> 5;
    const int xi = tid & 31;
    const int xc = xi >> 2;
    const int xq = xi & 3;

    float c = 0.0f, h = 0.0f;

    for (int t = 0; t < T_SEQ; t++) {
        const bool m = (t < L);

        // ---- input-projection preacts (loads issued early, hidden by MMA)
        float p0, p1, p2, p3;
        if (LAYER == 0) {
            int teff = (dir == 0) ? t : (m ? (L - 1 - t) : t);
            const float* xp = x + ((size_t)bglob * T_SEQ + teff) * 3;
            float x0 = xp[0], x1 = xp[1], x2 = xp[2];
            p0 = bs4[0] + wia[0] * x0 + wib[0] * x1 + wic[0] * x2;
            p1 = bs4[1] + wia[1] * x0 + wib[1] * x1 + wic[1] * x2;
            p2 = bs4[2] + wia[2] * x0 + wib[2] * x1 + wic[2] * x2;
            p3 = bs4[3] + wia[3] * x0 + wib[3] * x1 + wic[3] * x2;
        } else {
            const float* gp = g_gx + (((size_t)dir * T_SEQ + t) * NB + bglob) * 1024 + uglob;
            p0 = __ldg(gp);       p1 = __ldg(gp + 256);
            p2 = __ldg(gp + 512); p3 = __ldg(gp + 768);
        }

        // ---- recurrent matvec: 6 independent HMMA chains (3 passes x 2 j)
        float acc[6][4];
        #pragma unroll
        for (int i = 0; i < 6; i++) {
            acc[i][0] = 0.f; acc[i][1] = 0.f; acc[i][2] = 0.f; acc[i][3] = 0.f;
        }
        #pragma unroll
        for (int ks = 0; ks < 16; ks++) {
            uint32_t ah[4], al[4];
            ldsm4(ah, aBaseH + (uint32_t)ks * 32u);
            ldsm4(al, aBaseL + (uint32_t)ks * 32u);
            mma_bf16(acc[0], ah, bfh[ks][0][0], bfh[ks][0][1]);
            mma_bf16(acc[1], ah, bfl[ks][0][0], bfl[ks][0][1]);
            mma_bf16(acc[2], al, bfh[ks][0][0], bfh[ks][0][1]);
            mma_bf16(acc[3], ah, bfh[ks][1][0], bfh[ks][1][1]);
            mma_bf16(acc[4], ah, bfl[ks][1][0], bfl[ks][1][1]);
            mma_bf16(acc[5], al, bfh[ks][1][0], bfh[ks][1][1]);
        }

        // ---- dump gates (row g = batch; cols = r_local); rows g+8 = padding
        *reinterpret_cast<float2*>(&gates_s[g * 132 + w * 16 + 2 * t4]) =
            make_float2(acc[0][0] + acc[1][0] + acc[2][0],
                        acc[0][1] + acc[1][1] + acc[2][1]);
        *reinterpret_cast<float2*>(&gates_s[g * 132 + w * 16 + 8 + 2 * t4]) =
            make_float2(acc[3][0] + acc[4][0] + acc[5][0],
                        acc[3][1] + acc[4][1] + acc[5][1]);
        __syncthreads();

        // ---- gate nonlinearity + state update: thread (b_upd, u)
        float g0 = p0 + gates_s[b_upd * 132 + u];
        float g1 = p1 + gates_s[b_upd * 132 + 32 + u];
        float g2 = p2 + gates_s[b_upd * 132 + 64 + u];
        float g3 = p3 + gates_s[b_upd * 132 + 96 + u];
        float ig = sigf(g0), fg = sigf(g1);
        float gg = tanhf(g2), og = sigf(g3);
        float cn = fmaf(fg, c, ig * gg);
        float hn = og * tanhf(cn);
        if (m) { c = cn; h = hn; }

        // ---- publish slice, split cluster barrier around the global store
        const int p = t & 1;
        slice[p * 256 + tid] = h;
        asm volatile("barrier.cluster.arrive.aligned;" ::: "memory");

        if (LAYER == 0) {
            int pos = (dir == 0) ? t : (m ? (L - 1 - t) : t);
            float val = m ? h : 0.0f;
            __nv_bfloat16 hi = __float2bfloat16(val);
            __nv_bfloat16 lo = __float2bfloat16(val - __bfloat162float(hi));
            size_t idx = ((size_t)bglob * T_SEQ + pos) * 512 + dir * 256 + uglob;
            g_h1h[idx] = hi;
            g_h1l[idx] = lo;
        } else if (dir == 1 && t == 0) {
            g_feat[bglob * 512 + 256 + uglob] = h;
        }

        asm volatile("barrier.cluster.wait.aligned;" ::: "memory");

        // ---- gather fused with fp32 -> bf16 hi/lo convert, straight into A tiles
        {
            float* psl = cluster.map_shared_rank((float*)slice, (unsigned)xc);
            const float4* src = reinterpret_cast<const float4*>(
                psl + p * 256 + xb * 32 + xq * 8);
            float4 v0 = src[0];
            float4 v1 = src[1];
            uint4 hi4, lo4;
            hi4.x = pack_bf16(v0.x, v0.y);
            hi4.y = pack_bf16(v0.z, v0.w);
            hi4.z = pack_bf16(v1.x, v1.y);
            hi4.w = pack_bf16(v1.z, v1.w);
            lo4.x = pack_bf16(bf_res(v0.x), bf_res(v0.y));
            lo4.y = pack_bf16(bf_res(v0.z), bf_res(v0.w));
            lo4.z = pack_bf16(bf_res(v1.x), bf_res(v1.y));
            lo4.w = pack_bf16(bf_res(v1.z), bf_res(v1.w));
            *reinterpret_cast<uint4*>(&Ah[xb * 132 + xc * 16 + xq * 4]) = hi4;
            *reinterpret_cast<uint4*>(&Al[xb * 132 + xc * 16 + xq * 4]) = lo4;
        }
        __syncthreads();
    }

    if (LAYER == 1 && dir == 0)
        g_feat[bglob * 512 + uglob] = h;
}

// =====================================================================
// W_ih_l1 fp32 -> bf16 hi/lo split
// =====================================================================
__global__ void __launch_bounds__(256) conv_w1(const float* __restrict__ Wih)
{
    size_t i = (size_t)blockIdx.x * 1024 + threadIdx.x * 4;
    float4 v = *reinterpret_cast<const float4*>(Wih + i);
    float vv[4] = {v.x, v.y, v.z, v.w};
    #pragma unroll
    for (int k = 0; k < 4; k++) {
        __nv_bfloat16 hi = __float2bfloat16(vv[k]);
        __nv_bfloat16 lo = __float2bfloat16(vv[k] - __bfloat162float(hi));
        g_w1h[i + k] = hi;
        g_w1l[i + k] = lo;
    }
}

// =====================================================================
// Layer-1 input projection via HMMA (unchanged, validated).
// =====================================================================
__global__ void __launch_bounds__(256) gx_mma(
    const int* __restrict__ lengths,
    const float* __restrict__ bih, const float* __restrict__ bhh)
{
    __shared__ __align__(16) uint32_t Ah[64 * 20], Al[64 * 20];
    __shared__ __align__(16) uint32_t Bh[128 * 20], Bl[128 * 20];
    __shared__ float bias_s[128];

    const int tid  = threadIdx.x;
    const int wid  = tid >> 5;
    const int lane = tid & 31;
    const int g    = lane >> 2;
    const int t4   = lane & 3;
    const int n0   = blockIdx.x * 128;
    const int t    = blockIdx.y;
    const int dir  = blockIdx.z;

    const int m0 = (wid & 1) * 32;
    const int nw = (wid >> 1) * 32;

    const int ar = tid >> 2, ac = tid & 3;
    const int br = tid >> 1, bc = tid & 1;
    if (tid < 128) bias_s[tid] = bih[dir * 1024 + n0 + tid] + bhh[dir * 1024 + n0 + tid];

    const int La = lengths[ar];
    const int teff = dir ? ((t < La) ? (La - 1 - t) : t) : t;
    const uint4* a_h = (const uint4*)(g_h1h + ((size_t)ar * T_SEQ + teff) * 512) + ac;
    const uint4* a_l = (const uint4*)(g_h1l + ((size_t)ar * T_SEQ + teff) * 512) + ac;
    const uint4* b_h = (const uint4*)(g_w1h + ((size_t)(dir * 1024 + n0 + br)) * 512) + bc * 2;
    const uint4* b_l = (const uint4*)(g_w1l + ((size_t)(dir * 1024 + n0 + br)) * 512) + bc * 2;

    float acc[2][4][4];
    #pragma unroll
    for (int i = 0; i < 2; i++)
        #pragma unroll
        for (int j = 0; j < 4; j++)
            #pragma unroll
            for (int k = 0; k < 4; k++) acc[i][j][k] = 0.0f;

    uint4 vah = __ldg(a_h), val_ = __ldg(a_l);
    uint4 vbh0 = __ldg(b_h), vbh1 = __ldg(b_h + 1);
    uint4 vbl0 = __ldg(b_l), vbl1 = __ldg(b_l + 1);

    for (int kc = 0; kc < 16; kc++) {
        *reinterpret_cast<uint4*>(&Ah[ar * 20 + ac * 4]) = vah;
        *reinterpret_cast<uint4*>(&Al[ar * 20 + ac * 4]) = val_;
        *reinterpret_cast<uint4*>(&Bh[br * 20 + bc * 8])     = vbh0;
        *reinterpret_cast<uint4*>(&Bh[br * 20 + bc * 8 + 4]) = vbh1;
        *reinterpret_cast<uint4*>(&Bl[br * 20 + bc * 8])     = vbl0;
        *reinterpret_cast<uint4*>(&Bl[br * 20 + bc * 8 + 4]) = vbl1;
        __syncthreads();

        if (kc + 1 < 16) {
            vah  = __ldg(a_h + (kc + 1) * 4);
            val_ = __ldg(a_l + (kc + 1) * 4);
            vbh0 = __ldg(b_h + (kc + 1) * 4);
            vbh1 = __ldg(b_h + (kc + 1) * 4 + 1);
            vbl0 = __ldg(b_l + (kc + 1) * 4);
            vbl1 = __ldg(b_l + (kc + 1) * 4 + 1);
        }

        #pragma unroll
        for (int pass = 0; pass < 3; pass++) {
            const uint32_t* Am = (pass == 2) ? Al : Ah;
            const uint32_t* Bm = (pass == 1) ? Bl : Bh;
            #pragma unroll
            for (int ks = 0; ks < 2; ks++) {
                uint32_t a[2][4];
                #pragma unroll
                for (int mf = 0; mf < 2; mf++) {
                    int r = m0 + mf * 16 + g;
                    a[mf][0] = Am[r * 20 + ks * 8 + t4];
                    a[mf][1] = Am[(r + 8) * 20 + ks * 8 + t4];
                    a[mf][2] = Am[r * 20 + ks * 8 + t4 + 4];
                    a[mf][3] = Am[(r + 8) * 20 + ks * 8 + t4 + 4];
                }
                #pragma unroll
                for (int nf = 0; nf < 4; nf++) {
                    int rn = nw + nf * 8 + g;
                    uint32_t b0 = Bm[rn * 20 + ks * 8 + t4];
                    uint32_t b1 = Bm[rn * 20 + ks * 8 + t4 + 4];
                    mma_bf16(acc[0][nf], a[0], b0, b1);
                    mma_bf16(acc[1][nf], a[1], b0, b1);
                }
            }
        }
        __syncthreads();
    }

    float* gxp = g_gx + ((size_t)(dir * T_SEQ + t) * NB) * 1024 + n0;
    #pragma unroll
    for (int mf = 0; mf < 2; mf++) {
        int bi = m0 + mf * 16 + g;
        #pragma unroll
        for (int nf = 0; nf < 4; nf++) {
            int nn = nw + nf * 8 + t4 * 2;
            float bv0 = bias_s[nn], bv1 = bias_s[nn + 1];
            float2 v0 = make_float2(acc[mf][nf][0] + bv0, acc[mf][nf][1] + bv1);
            float2 v1 = make_float2(acc[mf][nf][2] + bv0, acc[mf][nf][3] + bv1);
            *reinterpret_cast<float2*>(gxp + (size_t)bi * 1024 + nn)       = v0;
            *reinterpret_cast<float2*>(gxp + (size_t)(bi + 8) * 1024 + nn) = v1;
        }
    }
}

// =====================================================================
// Head
// =====================================================================
__global__ void __launch_bounds__(256) head_fc1(const float* __restrict__ fc1_w,
                                                const float* __restrict__ fc1_b)
{
    __shared__ __align__(16) float fs[512];
    int b = blockIdx.x, n = threadIdx.x;
    for (int i = n; i < 512; i += 256) fs[i] = g_feat[b * 512 + i];
    __syncthreads();
    const float4* wp = reinterpret_cast<const float4*>(fc1_w + (size_t)n * 512);
    const float4* fp = reinterpret_cast<const float4*>(fs);
    float acc = fc1_b[n];
    #pragma unroll 4
    for (int k = 0; k < 128; k++) {
        float4 w4 = __ldg(wp + k);
        float4 f4 = fp[k];
        acc += w4.x * f4.x + w4.y * f4.y + w4.z * f4.z + w4.w * f4.w;
    }
    g_y[b * 256 + n] = fmaxf(acc, 0.0f);
}

__global__ void head_bn(const float* __restrict__ gamma, const float* __restrict__ beta)
{
    int n = threadIdx.x;
    float s = 0.0f, s2 = 0.0f;
    for (int b = 0; b < 64; b++) {
        float v = g_y[b * 256 + n];
        s += v; s2 += v * v;
    }
    float mean = s * 0.015625f;
    float var  = s2 * 0.015625f - mean * mean;
    float inv  = rsqrtf(var + 1e-5f);
    float ga = gamma[n] * inv, be = beta[n];
    for (int b = 0; b < 64; b++)
        g_y[b * 256 + n] = (g_y[b * 256 + n] - mean) * ga + be;
}

__global__ void __launch_bounds__(256) head_out(const float* __restrict__ W,
                                                const float* __restrict__ bias,
                                                float* __restrict__ out)
{
    __shared__ __align__(16) float ys[256];
    int b = blockIdx.x;
    ys[threadIdx.x] = g_y[b * 256 + threadIdx.x];
    __syncthreads();
    int o = threadIdx.x;
    if (o < 196) {
        const float4* wp = reinterpret_cast<const float4*>(W + (size_t)o * 256);
        const float4* yp = reinterpret_cast<const float4*>(ys);
        float acc = bias[o];
        #pragma unroll 4
        for (int k = 0; k < 64; k++) {
            float4 w4 = __ldg(wp + k);
            float4 y4 = yp[k];
            acc += w4.x * y4.x + w4.y * y4.y + w4.z * y4.z + w4.w * y4.w;
        }
        out[(size_t)b * 196 + o] = acc;
    }
}

// =====================================================================
extern "C" void kernel_launch(void* const* d_in, const int* in_sizes, int n_in,
                              void* d_out, int out_size)
{
    const float* x       = (const float*)d_in[0];
    const int*   lengths = (const int*)  d_in[1];
    const float* Wih0    = (const float*)d_in[2];
    const float* Whh0    = (const float*)d_in[3];
    const float* bih0    = (const float*)d_in[4];
    const float* bhh0    = (const float*)d_in[5];
    const float* Wih1    = (const float*)d_in[6];
    const float* Whh1    = (const float*)d_in[7];
    const float* bih1    = (const float*)d_in[8];
    const float* bhh1    = (const float*)d_in[9];
    const float* fc1_w   = (const float*)d_in[10];
    const float* fc1_b   = (const float*)d_in[11];
    const float* gamma   = (const float*)d_in[12];
    const float* beta    = (const float*)d_in[13];
    const float* fcow    = (const float*)d_in[14];
    const float* fcob    = (const float*)d_in[15];
    float* out = (float*)d_out;

    conv_w1<<<1024, 256>>>(Wih1);
    lstm_rec<0><<<128, 256>>>(x, lengths, Wih0, Whh0, bih0, bhh0);
    gx_mma<<<dim3(8, 1024, 2), 256>>>(lengths, bih1, bhh1);
    lstm_rec<1><<<128, 256>>>(x, lengths, Wih1, Whh1, bih1, bhh1);
    head_fc1<<<64, 256>>>(fc1_w, fc1_b);
    head_bn<<<1, 256>>>(gamma, beta);
    head_out<<<64, 256>>>(fcow, fcob, out);
}

// round 7
// speedup vs baseline: 1.5275x; 1.1587x over previous
#include <cuda_runtime.h>
#include <cuda_bf16.h>
#include <cooperative_groups.h>
#include <cstdint>
#include <cstddef>

namespace cg = cooperative_groups;

#define HID   256
#define T_SEQ 1024
#define NB    64

// ---------------- scratch (device globals; no allocation) ----------------
__device__ __nv_bfloat16 g_h1h[(size_t)NB * T_SEQ * 512];   // layer-0 out, bf16 hi
__device__ __nv_bfloat16 g_h1l[(size_t)NB * T_SEQ * 512];   // layer-0 out, bf16 lo
__device__ __nv_bfloat16 g_w1h[(size_t)2 * 1024 * 512];     // W_ih_l1 bf16 hi
__device__ __nv_bfloat16 g_w1l[(size_t)2 * 1024 * 512];     // W_ih_l1 bf16 lo
__device__ float g_gx[(size_t)2 * T_SEQ * NB * 1024];       // layer-1 projected gates
__device__ float g_feat[NB * 512];
__device__ float g_y[NB * 256];

__device__ __forceinline__ float sigf(float x) {
    return __fdividef(1.0f, 1.0f + __expf(-x));
}

// mma.sync m16n8k16 row.col bf16 -> f32 (validated fragment layout)
__device__ __forceinline__ void mma_bf16(float* c, const uint32_t* a,
                                         uint32_t b0, uint32_t b1) {
    asm volatile(
        "mma.sync.aligned.m16n8k16.row.col.f32.bf16.bf16.f32 "
        "{%0,%1,%2,%3}, {%4,%5,%6,%7}, {%8,%9}, {%0,%1,%2,%3};"
        : "+f"(c[0]), "+f"(c[1]), "+f"(c[2]), "+f"(c[3])
        : "r"(a[0]), "r"(a[1]), "r"(a[2]), "r"(a[3]), "r"(b0), "r"(b1));
}

// ldmatrix x4: canonical A-operand load for m16n8k16 (row-major 16x16 bf16)
__device__ __forceinline__ void ldsm4(uint32_t* r, uint32_t addr) {
    asm volatile(
        "ldmatrix.sync.aligned.m8n8.x4.shared.b16 {%0,%1,%2,%3}, [%4];"
        : "=r"(r[0]), "=r"(r[1]), "=r"(r[2]), "=r"(r[3]) : "r"(addr));
}

__device__ __forceinline__ uint32_t smem_u32(const void* p) {
    uint32_t a;
    asm("{ .reg .u64 t; cvta.to.shared.u64 t, %1; cvt.u32.u64 %0, t; }" : "=r"(a) : "l"(p));
    return a;
}

__device__ __forceinline__ uint32_t pack_bf16(float a, float b) {
    __nv_bfloat162 v = __floats2bfloat162_rn(a, b);
    return *reinterpret_cast<uint32_t*>(&v);
}
__device__ __forceinline__ float bf_res(float x) {
    return x - __bfloat162float(__float2bfloat16(x));
}

// =====================================================================
// Recurrent LSTM on tensor cores. Cluster of 8 CTAs = (dir, batch-group).
// A tile M=16 packs: rows 0-7 = h_hi(8 batches), rows 8-15 = h_lo.
// Two MMA passes (x W_hi, x W_lo) give the full split-bf16 product with
// 100% M utilization: gate = (AhWh + AlWh) + (AhWl + AlWl).
// W_hh fragments (bf16 hi/lo) register-stationary.
// =====================================================================
template<int LAYER>
__global__ void __launch_bounds__(256, 1) __cluster_dims__(8, 1, 1)
lstm_rec(const float* __restrict__ x, const int* __restrict__ lengths,
         const float* __restrict__ Wih, const float* __restrict__ Whh,
         const float* __restrict__ bih, const float* __restrict__ bhh)
{
    __shared__ __align__(16) uint32_t Ahl[16 * 132];    // rows 0-7 hi, 8-15 lo
    __shared__ __align__(16) float slice[2 * 8 * 32];   // double-buffered own h slice
    __shared__ __align__(16) float gates_s[8 * 132];    // [b][r_local]

    cg::cluster_group cluster = cg::this_cluster();
    const int tid   = threadIdx.x;
    const int w     = tid >> 5;
    const int lane  = tid & 31;
    const int g     = lane >> 2;
    const int t4    = lane & 3;
    const int crank = blockIdx.x & 7;
    const int group = blockIdx.x >> 3;
    const int dir   = group >> 3;
    const int bg    = group & 7;
    const int b_upd = w;                     // update-thread batch
    const int u     = lane;                  // update-thread unit (local)
    const int uglob = crank * 32 + u;
    const int bglob = bg * 8 + b_upd;
    const int L     = lengths[bglob];

    // ---- W_hh fragments into registers: bfh/bfl[ks][j][slot]
    uint32_t bfh[16][2][2], bfl[16][2][2];
    #pragma unroll
    for (int j = 0; j < 2; j++) {
        int rl   = w * 16 + j * 8 + g;
        int grow = dir * 1024 + ((rl >> 5) << 8) + crank * 32 + (rl & 31);
        const float* wp = Whh + (size_t)grow * 256;
        #pragma unroll
        for (int ks = 0; ks < 16; ks++) {
            #pragma unroll
            for (int s = 0; s < 2; s++) {
                int kp = ks * 8 + t4 + s * 4;
                float2 wv = *reinterpret_cast<const float2*>(wp + kp * 2);
                bfh[ks][j][s] = pack_bf16(wv.x, wv.y);
                bfl[ks][j][s] = pack_bf16(bf_res(wv.x), bf_res(wv.y));
            }
        }
    }

    // ---- layer-0 input projection params (IN = 3) for update thread
    float wia[4], wib[4], wic[4], bs4[4];
    if (LAYER == 0) {
        #pragma unroll
        for (int q = 0; q < 4; q++) {
            int row = dir * 1024 + q * 256 + uglob;
            wia[q] = Wih[(size_t)row * 3 + 0];
            wib[q] = Wih[(size_t)row * 3 + 1];
            wic[q] = Wih[(size_t)row * 3 + 2];
            bs4[q] = bih[row] + bhh[row];
        }
    }

    for (int i = tid; i < 16 * 132; i += 256) Ahl[i] = 0u;
    __syncthreads();

    // ldmatrix per-lane base address (rows 0-15 all live now)
    const int lrow  = lane & 15;
    const int lcoff = (lane >> 4) * 4;
    const uint32_t aBase = smem_u32(Ahl) + (uint32_t)(lrow * 132 + lcoff) * 4u;

    // DSMEM gather mapping: thread -> (batch xb, peer xc, unit-octet xq)
    const int xb = tid >> 5;
    const int xi = tid & 31;
    const int xc = xi >> 2;
    const int xq = xi & 3;

    const float* gx_base = g_gx + ((size_t)dir * T_SEQ * NB + bglob) * 1024 + uglob;

    float c = 0.0f, h = 0.0f;

    // ---- prefetch inputs for step 0
    float p0, p1, p2, p3;
    if (LAYER == 1) {
        const float* gp = gx_base;           // t = 0
        p0 = __ldg(gp);       p1 = __ldg(gp + 256);
        p2 = __ldg(gp + 512); p3 = __ldg(gp + 768);
    }

    for (int t = 0; t < T_SEQ; t++) {
        const bool m = (t < L);

        if (LAYER == 0) {
            int teff = (dir == 0) ? t : (m ? (L - 1 - t) : t);
            const float* xp = x + ((size_t)bglob * T_SEQ + teff) * 3;
            float x0 = xp[0], x1 = xp[1], x2 = xp[2];
            p0 = bs4[0] + wia[0] * x0 + wib[0] * x1 + wic[0] * x2;
            p1 = bs4[1] + wia[1] * x0 + wib[1] * x1 + wic[1] * x2;
            p2 = bs4[2] + wia[2] * x0 + wib[2] * x1 + wic[2] * x2;
            p3 = bs4[3] + wia[3] * x0 + wib[3] * x1 + wic[3] * x2;
        }

        // ---- recurrent matvec: 2 passes x 2 j = 4 independent HMMA chains
        float acc0[4] = {0.f, 0.f, 0.f, 0.f};   // j0, x W_hi
        float acc1[4] = {0.f, 0.f, 0.f, 0.f};   // j0, x W_lo
        float acc2[4] = {0.f, 0.f, 0.f, 0.f};   // j1, x W_hi
        float acc3[4] = {0.f, 0.f, 0.f, 0.f};   // j1, x W_lo
        #pragma unroll
        for (int ks = 0; ks < 16; ks++) {
            uint32_t a[4];
            ldsm4(a, aBase + (uint32_t)ks * 32u);
            mma_bf16(acc0, a, bfh[ks][0][0], bfh[ks][0][1]);
            mma_bf16(acc1, a, bfl[ks][0][0], bfl[ks][0][1]);
            mma_bf16(acc2, a, bfh[ks][1][0], bfh[ks][1][1]);
            mma_bf16(acc3, a, bfl[ks][1][0], bfl[ks][1][1]);
        }

        // ---- dump gates: row g = batch; c[0],c[1] row g (hi), c[2],c[3] row g+8 (lo)
        *reinterpret_cast<float2*>(&gates_s[g * 132 + w * 16 + 2 * t4]) =
            make_float2(acc0[0] + acc0[2] + acc1[0] + acc1[2],
                        acc0[1] + acc0[3] + acc1[1] + acc1[3]);
        *reinterpret_cast<float2*>(&gates_s[g * 132 + w * 16 + 8 + 2 * t4]) =
            make_float2(acc2[0] + acc2[2] + acc3[0] + acc3[2],
                        acc2[1] + acc2[3] + acc3[1] + acc3[3]);
        __syncthreads();

        // ---- gate nonlinearity + state update: thread (b_upd, u)
        float g0 = p0 + gates_s[b_upd * 132 + u];
        float g1 = p1 + gates_s[b_upd * 132 + 32 + u];
        float g2 = p2 + gates_s[b_upd * 132 + 64 + u];
        float g3 = p3 + gates_s[b_upd * 132 + 96 + u];
        float ig = sigf(g0), fg = sigf(g1);
        float gg = tanhf(g2), og = sigf(g3);
        float cn = fmaf(fg, c, ig * gg);
        float hn = og * tanhf(cn);
        if (m) { c = cn; h = hn; }

        // ---- issue next-step input loads now (hidden by barrier+gather+MMA)
        if (LAYER == 1) {
            int tn = (t + 1 < T_SEQ) ? t + 1 : t;
            const float* gp = gx_base + (size_t)tn * NB * 1024;
            p0 = __ldg(gp);       p1 = __ldg(gp + 256);
            p2 = __ldg(gp + 512); p3 = __ldg(gp + 768);
        }

        // ---- publish slice, split cluster barrier around the global store
        const int p = t & 1;
        slice[p * 256 + tid] = h;
        asm volatile("barrier.cluster.arrive.aligned;" ::: "memory");

        if (LAYER == 0) {
            int pos = (dir == 0) ? t : (m ? (L - 1 - t) : t);
            float val = m ? h : 0.0f;
            __nv_bfloat16 hi = __float2bfloat16(val);
            __nv_bfloat16 lo = __float2bfloat16(val - __bfloat162float(hi));
            size_t idx = ((size_t)bglob * T_SEQ + pos) * 512 + dir * 256 + uglob;
            g_h1h[idx] = hi;
            g_h1l[idx] = lo;
        } else if (dir == 1 && t == 0) {
            g_feat[bglob * 512 + 256 + uglob] = h;
        }

        asm volatile("barrier.cluster.wait.aligned;" ::: "memory");

        // ---- gather fused with fp32 -> bf16 hi/lo convert: hi -> row xb, lo -> row xb+8
        {
            float* psl = cluster.map_shared_rank((float*)slice, (unsigned)xc);
            const float4* src = reinterpret_cast<const float4*>(
                psl + p * 256 + xb * 32 + xq * 8);
            float4 v0 = src[0];
            float4 v1 = src[1];
            uint4 hi4, lo4;
            hi4.x = pack_bf16(v0.x, v0.y);
            hi4.y = pack_bf16(v0.z, v0.w);
            hi4.z = pack_bf16(v1.x, v1.y);
            hi4.w = pack_bf16(v1.z, v1.w);
            lo4.x = pack_bf16(bf_res(v0.x), bf_res(v0.y));
            lo4.y = pack_bf16(bf_res(v0.z), bf_res(v0.w));
            lo4.z = pack_bf16(bf_res(v1.x), bf_res(v1.y));
            lo4.w = pack_bf16(bf_res(v1.z), bf_res(v1.w));
            *reinterpret_cast<uint4*>(&Ahl[xb * 132 + xc * 16 + xq * 4])       = hi4;
            *reinterpret_cast<uint4*>(&Ahl[(xb + 8) * 132 + xc * 16 + xq * 4]) = lo4;
        }
        __syncthreads();
    }

    if (LAYER == 1 && dir == 0)
        g_feat[bglob * 512 + uglob] = h;
}

// =====================================================================
// W_ih_l1 fp32 -> bf16 hi/lo split
// =====================================================================
__global__ void __launch_bounds__(256) conv_w1(const float* __restrict__ Wih)
{
    size_t i = (size_t)blockIdx.x * 1024 + threadIdx.x * 4;
    float4 v = *reinterpret_cast<const float4*>(Wih + i);
    float vv[4] = {v.x, v.y, v.z, v.w};
    #pragma unroll
    for (int k = 0; k < 4; k++) {
        __nv_bfloat16 hi = __float2bfloat16(vv[k]);
        __nv_bfloat16 lo = __float2bfloat16(vv[k] - __bfloat162float(hi));
        g_w1h[i + k] = hi;
        g_w1l[i + k] = lo;
    }
}

// =====================================================================
// Layer-1 input projection via HMMA (unchanged, validated).
// =====================================================================
__global__ void __launch_bounds__(256) gx_mma(
    const int* __restrict__ lengths,
    const float* __restrict__ bih, const float* __restrict__ bhh)
{
    __shared__ __align__(16) uint32_t Ah[64 * 20], Al[64 * 20];
    __shared__ __align__(16) uint32_t Bh[128 * 20], Bl[128 * 20];
    __shared__ float bias_s[128];

    const int tid  = threadIdx.x;
    const int wid  = tid >> 5;
    const int lane = tid & 31;
    const int g    = lane >> 2;
    const int t4   = lane & 3;
    const int n0   = blockIdx.x * 128;
    const int t    = blockIdx.y;
    const int dir  = blockIdx.z;

    const int m0 = (wid & 1) * 32;
    const int nw = (wid >> 1) * 32;

    const int ar = tid >> 2, ac = tid & 3;
    const int br = tid >> 1, bc = tid & 1;
    if (tid < 128) bias_s[tid] = bih[dir * 1024 + n0 + tid] + bhh[dir * 1024 + n0 + tid];

    const int La = lengths[ar];
    const int teff = dir ? ((t < La) ? (La - 1 - t) : t) : t;
    const uint4* a_h = (const uint4*)(g_h1h + ((size_t)ar * T_SEQ + teff) * 512) + ac;
    const uint4* a_l = (const uint4*)(g_h1l + ((size_t)ar * T_SEQ + teff) * 512) + ac;
    const uint4* b_h = (const uint4*)(g_w1h + ((size_t)(dir * 1024 + n0 + br)) * 512) + bc * 2;
    const uint4* b_l = (const uint4*)(g_w1l + ((size_t)(dir * 1024 + n0 + br)) * 512) + bc * 2;

    float acc[2][4][4];
    #pragma unroll
    for (int i = 0; i < 2; i++)
        #pragma unroll
        for (int j = 0; j < 4; j++)
            #pragma unroll
            for (int k = 0; k < 4; k++) acc[i][j][k] = 0.0f;

    uint4 vah = __ldg(a_h), val_ = __ldg(a_l);
    uint4 vbh0 = __ldg(b_h), vbh1 = __ldg(b_h + 1);
    uint4 vbl0 = __ldg(b_l), vbl1 = __ldg(b_l + 1);

    for (int kc = 0; kc < 16; kc++) {
        *reinterpret_cast<uint4*>(&Ah[ar * 20 + ac * 4]) = vah;
        *reinterpret_cast<uint4*>(&Al[ar * 20 + ac * 4]) = val_;
        *reinterpret_cast<uint4*>(&Bh[br * 20 + bc * 8])     = vbh0;
        *reinterpret_cast<uint4*>(&Bh[br * 20 + bc * 8 + 4]) = vbh1;
        *reinterpret_cast<uint4*>(&Bl[br * 20 + bc * 8])     = vbl0;
        *reinterpret_cast<uint4*>(&Bl[br * 20 + bc * 8 + 4]) = vbl1;
        __syncthreads();

        if (kc + 1 < 16) {
            vah  = __ldg(a_h + (kc + 1) * 4);
            val_ = __ldg(a_l + (kc + 1) * 4);
            vbh0 = __ldg(b_h + (kc + 1) * 4);
            vbh1 = __ldg(b_h + (kc + 1) * 4 + 1);
            vbl0 = __ldg(b_l + (kc + 1) * 4);
            vbl1 = __ldg(b_l + (kc + 1) * 4 + 1);
        }

        #pragma unroll
        for (int pass = 0; pass < 3; pass++) {
            const uint32_t* Am = (pass == 2) ? Al : Ah;
            const uint32_t* Bm = (pass == 1) ? Bl : Bh;
            #pragma unroll
            for (int ks = 0; ks < 2; ks++) {
                uint32_t a[2][4];
                #pragma unroll
                for (int mf = 0; mf < 2; mf++) {
                    int r = m0 + mf * 16 + g;
                    a[mf][0] = Am[r * 20 + ks * 8 + t4];
                    a[mf][1] = Am[(r + 8) * 20 + ks * 8 + t4];
                    a[mf][2] = Am[r * 20 + ks * 8 + t4 + 4];
                    a[mf][3] = Am[(r + 8) * 20 + ks * 8 + t4 + 4];
                }
                #pragma unroll
                for (int nf = 0; nf < 4; nf++) {
                    int rn = nw + nf * 8 + g;
                    uint32_t b0 = Bm[rn * 20 + ks * 8 + t4];
                    uint32_t b1 = Bm[rn * 20 + ks * 8 + t4 + 4];
                    mma_bf16(acc[0][nf], a[0], b0, b1);
                    mma_bf16(acc[1][nf], a[1], b0, b1);
                }
            }
        }
        __syncthreads();
    }

    float* gxp = g_gx + ((size_t)(dir * T_SEQ + t) * NB) * 1024 + n0;
    #pragma unroll
    for (int mf = 0; mf < 2; mf++) {
        int bi = m0 + mf * 16 + g;
        #pragma unroll
        for (int nf = 0; nf < 4; nf++) {
            int nn = nw + nf * 8 + t4 * 2;
            float bv0 = bias_s[nn], bv1 = bias_s[nn + 1];
            float2 v0 = make_float2(acc[mf][nf][0] + bv0, acc[mf][nf][1] + bv1);
            float2 v1 = make_float2(acc[mf][nf][2] + bv0, acc[mf][nf][3] + bv1);
            *reinterpret_cast<float2*>(gxp + (size_t)bi * 1024 + nn)       = v0;
            *reinterpret_cast<float2*>(gxp + (size_t)(bi + 8) * 1024 + nn) = v1;
        }
    }
}

// =====================================================================
// Head
// =====================================================================
__global__ void __launch_bounds__(256) head_fc1(const float* __restrict__ fc1_w,
                                                const float* __restrict__ fc1_b)
{
    __shared__ __align__(16) float fs[512];
    int b = blockIdx.x, n = threadIdx.x;
    for (int i = n; i < 512; i += 256) fs[i] = g_feat[b * 512 + i];
    __syncthreads();
    const float4* wp = reinterpret_cast<const float4*>(fc1_w + (size_t)n * 512);
    const float4* fp = reinterpret_cast<const float4*>(fs);
    float acc = fc1_b[n];
    #pragma unroll 4
    for (int k = 0; k < 128; k++) {
        float4 w4 = __ldg(wp + k);
        float4 f4 = fp[k];
        acc += w4.x * f4.x + w4.y * f4.y + w4.z * f4.z + w4.w * f4.w;
    }
    g_y[b * 256 + n] = fmaxf(acc, 0.0f);
}

__global__ void head_bn(const float* __restrict__ gamma, const float* __restrict__ beta)
{
    int n = threadIdx.x;
    float s = 0.0f, s2 = 0.0f;
    for (int b = 0; b < 64; b++) {
        float v = g_y[b * 256 + n];
        s += v; s2 += v * v;
    }
    float mean = s * 0.015625f;
    float var  = s2 * 0.015625f - mean * mean;
    float inv  = rsqrtf(var + 1e-5f);
    float ga = gamma[n] * inv, be = beta[n];
    for (int b = 0; b < 64; b++)
        g_y[b * 256 + n] = (g_y[b * 256 + n] - mean) * ga + be;
}

__global__ void __launch_bounds__(256) head_out(const float* __restrict__ W,
                                                const float* __restrict__ bias,
                                                float* __restrict__ out)
{
    __shared__ __align__(16) float ys[256];
    int b = blockIdx.x;
    ys[threadIdx.x] = g_y[b * 256 + threadIdx.x];
    __syncthreads();
    int o = threadIdx.x;
    if (o < 196) {
        const float4* wp = reinterpret_cast<const float4*>(W + (size_t)o * 256);
        const float4* yp = reinterpret_cast<const float4*>(ys);
        float acc = bias[o];
        #pragma unroll 4
        for (int k = 0; k < 64; k++) {
            float4 w4 = __ldg(wp + k);
            float4 y4 = yp[k];
            acc += w4.x * y4.x + w4.y * y4.y + w4.z * y4.z + w4.w * y4.w;
        }
        out[(size_t)b * 196 + o] = acc;
    }
}

// =====================================================================
extern "C" void kernel_launch(void* const* d_in, const int* in_sizes, int n_in,
                              void* d_out, int out_size)
{
    const float* x       = (const float*)d_in[0];
    const int*   lengths = (const int*)  d_in[1];
    const float* Wih0    = (const float*)d_in[2];
    const float* Whh0    = (const float*)d_in[3];
    const float* bih0    = (const float*)d_in[4];
    const float* bhh0    = (const float*)d_in[5];
    const float* Wih1    = (const float*)d_in[6];
    const float* Whh1    = (const float*)d_in[7];
    const float* bih1    = (const float*)d_in[8];
    const float* bhh1    = (const float*)d_in[9];
    const float* fc1_w   = (const float*)d_in[10];
    const float* fc1_b   = (const float*)d_in[11];
    const float* gamma   = (const float*)d_in[12];
    const float* beta    = (const float*)d_in[13];
    const float* fcow    = (const float*)d_in[14];
    const float* fcob    = (const float*)d_in[15];
    float* out = (float*)d_out;

    conv_w1<<<1024, 256>>>(Wih1);
    lstm_rec<0><<<128, 256>>>(x, lengths, Wih0, Whh0, bih0, bhh0);
    gx_mma<<<dim3(8, 1024, 2), 256>>>(lengths, bih1, bhh1);
    lstm_rec<1><<<128, 256>>>(x, lengths, Wih1, Whh1, bih1, bhh1);
    head_fc1<<<64, 256>>>(fc1_w, fc1_b);
    head_bn<<<1, 256>>>(gamma, beta);
    head_out<<<64, 256>>>(fcow, fcob, out);
}

// round 8
// speedup vs baseline: 1.5401x; 1.0082x over previous
#include <cuda_runtime.h>
#include <cuda_bf16.h>
#include <cooperative_groups.h>
#include <cstdint>
#include <cstddef>

namespace cg = cooperative_groups;

#define HID   256
#define T_SEQ 1024
#define NB    64

// ---------------- scratch (device globals; no allocation) ----------------
__device__ __nv_bfloat16 g_h1h[(size_t)NB * T_SEQ * 512];   // layer-0 out, bf16 hi
__device__ __nv_bfloat16 g_h1l[(size_t)NB * T_SEQ * 512];   // layer-0 out, bf16 lo
__device__ __nv_bfloat16 g_w1h[(size_t)2 * 1024 * 512];     // W_ih_l1 bf16 hi
__device__ __nv_bfloat16 g_w1l[(size_t)2 * 1024 * 512];     // W_ih_l1 bf16 lo
__device__ float g_gx[(size_t)2 * T_SEQ * NB * 1024];       // layer-1 projected gates
__device__ float g_feat[NB * 512];
__device__ float g_y[NB * 256];

__device__ __forceinline__ float sigf(float x) {
    return __fdividef(1.0f, 1.0f + __expf(-x));
}

// mma.sync m16n8k16 row.col bf16 -> f32 (validated fragment layout)
__device__ __forceinline__ void mma_bf16(float* c, const uint32_t* a,
                                         uint32_t b0, uint32_t b1) {
    asm volatile(
        "mma.sync.aligned.m16n8k16.row.col.f32.bf16.bf16.f32 "
        "{%0,%1,%2,%3}, {%4,%5,%6,%7}, {%8,%9}, {%0,%1,%2,%3};"
        : "+f"(c[0]), "+f"(c[1]), "+f"(c[2]), "+f"(c[3])
        : "r"(a[0]), "r"(a[1]), "r"(a[2]), "r"(a[3]), "r"(b0), "r"(b1));
}

// ldmatrix x4: canonical A-operand load for m16n8k16 (row-major 16x16 bf16)
__device__ __forceinline__ void ldsm4(uint32_t* r, uint32_t addr) {
    asm volatile(
        "ldmatrix.sync.aligned.m8n8.x4.shared.b16 {%0,%1,%2,%3}, [%4];"
        : "=r"(r[0]), "=r"(r[1]), "=r"(r[2]), "=r"(r[3]) : "r"(addr));
}

__device__ __forceinline__ uint32_t smem_u32(const void* p) {
    uint32_t a;
    asm("{ .reg .u64 t; cvta.to.shared.u64 t, %1; cvt.u32.u64 %0, t; }" : "=r"(a) : "l"(p));
    return a;
}

__device__ __forceinline__ uint32_t pack_bf16(float a, float b) {
    __nv_bfloat162 v = __floats2bfloat162_rn(a, b);
    return *reinterpret_cast<uint32_t*>(&v);
}
__device__ __forceinline__ float bf_res(float x) {
    return x - __bfloat162float(__float2bfloat16(x));
}

#define MBAR_INIT(a, c) \
    asm volatile("mbarrier.init.shared.b64 [%0], %1;" :: "r"(a), "r"((uint32_t)(c)) : "memory")

// cluster-scope acquire wait (spin on try_wait)
#define MBAR_WAIT_CL(a, par) do {                                                   \
    uint32_t _m = (a), _p = (par);                                                  \
    asm volatile("{\n\t.reg .pred P1;\n\t"                                          \
        "WLC_%=:\n\t"                                                               \
        "mbarrier.try_wait.parity.acquire.cluster.shared::cta.b64 P1, [%0], %1;\n\t"\
        "@P1 bra.uni WDC_%=;\n\t"                                                   \
        "bra.uni WLC_%=;\n\t"                                                       \
        "WDC_%=:\n\t}" :: "r"(_m), "r"(_p) : "memory");                             \
} while (0)

#define MBAR_ARRIVE_REMOTE(a) \
    asm volatile("mbarrier.arrive.release.cluster.shared::cluster.b64 _, [%0];" \
                 :: "r"(a) : "memory")

#define CLUSTER_ARRIVE() asm volatile("barrier.cluster.arrive.aligned;" ::: "memory")
#define CLUSTER_WAIT()   asm volatile("barrier.cluster.wait.aligned;" ::: "memory")

// =====================================================================
// Recurrent LSTM on tensor cores, push-based mbarrier exchange.
// Cluster of 8 CTAs = (dir, batch-group). A tile M=16: rows 0-7 h_hi,
// rows 8-15 h_lo (8 batches). 2 MMA passes (W_hi, W_lo), W in registers.
// Per step: [wait mbar] -> ldsm+64 HMMA -> gates dump -> __syncthreads ->
// update -> push bf16 hi/lo into ALL peers' tile[(t+1)&1] via
// st.shared::cluster -> per-warp remote arrives -> (h1 store overlap).
// =====================================================================
template<int LAYER>
__global__ void __launch_bounds__(256, 1) __cluster_dims__(8, 1, 1)
lstm_rec(const float* __restrict__ x, const int* __restrict__ lengths,
         const float* __restrict__ Wih, const float* __restrict__ Whh,
         const float* __restrict__ bih, const float* __restrict__ bhh)
{
    __shared__ __align__(16) uint32_t Ahl[2][16 * 132];  // double-buffered A tiles
    __shared__ __align__(16) float gates_s[8 * 132];     // [b][r_local]
    __shared__ __align__(8)  uint64_t mbars[2];

    const int tid   = threadIdx.x;
    const int w     = tid >> 5;
    const int lane  = tid & 31;
    const int g     = lane >> 2;
    const int t4    = lane & 3;
    uint32_t crank;
    asm("mov.u32 %0, %%cluster_ctarank;" : "=r"(crank));
    const int group = blockIdx.x >> 3;
    const int dir   = group >> 3;
    const int bg    = group & 7;
    const int b_upd = w;
    const int u     = lane;
    const int uglob = (int)crank * 32 + u;
    const int bglob = bg * 8 + b_upd;
    const int L     = lengths[bglob];

    // ---- W_hh fragments into registers
    uint32_t bfh[16][2][2], bfl[16][2][2];
    #pragma unroll
    for (int j = 0; j < 2; j++) {
        int rl   = w * 16 + j * 8 + g;
        int grow = dir * 1024 + ((rl >> 5) << 8) + (int)crank * 32 + (rl & 31);
        const float* wp = Whh + (size_t)grow * 256;
        #pragma unroll
        for (int ks = 0; ks < 16; ks++) {
            #pragma unroll
            for (int s = 0; s < 2; s++) {
                int kp = ks * 8 + t4 + s * 4;
                float2 wv = *reinterpret_cast<const float2*>(wp + kp * 2);
                bfh[ks][j][s] = pack_bf16(wv.x, wv.y);
                bfl[ks][j][s] = pack_bf16(bf_res(wv.x), bf_res(wv.y));
            }
        }
    }

    // ---- layer-0 input projection params (IN = 3)
    float wia[4], wib[4], wic[4], bs4[4];
    if (LAYER == 0) {
        #pragma unroll
        for (int q = 0; q < 4; q++) {
            int row = dir * 1024 + q * 256 + uglob;
            wia[q] = Wih[(size_t)row * 3 + 0];
            wib[q] = Wih[(size_t)row * 3 + 1];
            wic[q] = Wih[(size_t)row * 3 + 2];
            bs4[q] = bih[row] + bhh[row];
        }
    }

    for (int i = tid; i < 2 * 16 * 132; i += 256) ((uint32_t*)Ahl)[i] = 0u;
    const uint32_t mbase = smem_u32(mbars);
    if (tid == 0) {
        MBAR_INIT(mbase, 64);
        MBAR_INIT(mbase + 8, 64);
        asm volatile("fence.mbarrier_init.release.cluster;" ::: "memory");
    }
    __syncthreads();
    CLUSTER_ARRIVE();
    CLUSTER_WAIT();

    // ---- precomputed peer addresses (tiles + mbars)
    const uint32_t tbase = smem_u32(Ahl);
    uint32_t peerT[8], peerM[8];
    #pragma unroll
    for (int pe = 0; pe < 8; pe++) {
        asm("mapa.shared::cluster.u32 %0, %1, %2;" : "=r"(peerT[pe]) : "r"(tbase), "r"(pe));
        asm("mapa.shared::cluster.u32 %0, %1, %2;" : "=r"(peerM[pe]) : "r"(mbase), "r"(pe));
    }

    // ldmatrix per-lane bases for both tile buffers
    const int lrow  = lane & 15;
    const int lcoff = (lane >> 4) * 4;
    const uint32_t aB0 = tbase + (uint32_t)(lrow * 132 + lcoff) * 4u;
    const uint32_t aB1 = aB0 + 2112u * 4u;

    const float* gx_base = g_gx + ((size_t)dir * T_SEQ * NB + bglob) * 1024 + uglob;
    const int kp_sh = lane & 15;            // shfl source pair for push

    float c = 0.0f, h = 0.0f;
    int ph0 = 0, ph1 = 0;

    float p0, p1, p2, p3;
    if (LAYER == 1) {
        const float* gp = gx_base;
        p0 = __ldg(gp);       p1 = __ldg(gp + 256);
        p2 = __ldg(gp + 512); p3 = __ldg(gp + 768);
    }

    for (int t = 0; t < T_SEQ; t++) {
        const bool m = (t < L);

        if (LAYER == 0) {
            int teff = (dir == 0) ? t : (m ? (L - 1 - t) : t);
            const float* xp = x + ((size_t)bglob * T_SEQ + teff) * 3;
            float x0 = xp[0], x1 = xp[1], x2 = xp[2];
            p0 = bs4[0] + wia[0] * x0 + wib[0] * x1 + wic[0] * x2;
            p1 = bs4[1] + wia[1] * x0 + wib[1] * x1 + wic[1] * x2;
            p2 = bs4[2] + wia[2] * x0 + wib[2] * x1 + wic[2] * x2;
            p3 = bs4[3] + wia[3] * x0 + wib[3] * x1 + wic[3] * x2;
        }

        // ---- wait for this step's A tile (all peers pushed); t=0 reads zeros
        if (t > 0) {
            if (t & 1) { MBAR_WAIT_CL(mbase + 8, ph1); ph1 ^= 1; }
            else       { MBAR_WAIT_CL(mbase,     ph0); ph0 ^= 1; }
        }
        const uint32_t aBase = (t & 1) ? aB1 : aB0;

        // ---- recurrent matvec: 2 passes x 2 j = 4 independent HMMA chains
        float acc0[4] = {0.f, 0.f, 0.f, 0.f};
        float acc1[4] = {0.f, 0.f, 0.f, 0.f};
        float acc2[4] = {0.f, 0.f, 0.f, 0.f};
        float acc3[4] = {0.f, 0.f, 0.f, 0.f};
        #pragma unroll
        for (int ks = 0; ks < 16; ks++) {
            uint32_t a[4];
            ldsm4(a, aBase + (uint32_t)ks * 32u);
            mma_bf16(acc0, a, bfh[ks][0][0], bfh[ks][0][1]);
            mma_bf16(acc1, a, bfl[ks][0][0], bfl[ks][0][1]);
            mma_bf16(acc2, a, bfh[ks][1][0], bfh[ks][1][1]);
            mma_bf16(acc3, a, bfl[ks][1][0], bfl[ks][1][1]);
        }

        // ---- dump gates: row g = batch; c[0,1]=hi rows, c[2,3]=lo rows
        *reinterpret_cast<float2*>(&gates_s[g * 132 + w * 16 + 2 * t4]) =
            make_float2(acc0[0] + acc0[2] + acc1[0] + acc1[2],
                        acc0[1] + acc0[3] + acc1[1] + acc1[3]);
        *reinterpret_cast<float2*>(&gates_s[g * 132 + w * 16 + 8 + 2 * t4]) =
            make_float2(acc2[0] + acc2[2] + acc3[0] + acc3[2],
                        acc2[1] + acc2[3] + acc3[1] + acc3[3]);
        __syncthreads();

        // ---- gate nonlinearity + state update: thread (b_upd, u)
        float g0 = p0 + gates_s[b_upd * 132 + u];
        float g1 = p1 + gates_s[b_upd * 132 + 32 + u];
        float g2 = p2 + gates_s[b_upd * 132 + 64 + u];
        float g3 = p3 + gates_s[b_upd * 132 + 96 + u];
        float ig = sigf(g0), fg = sigf(g1);
        float gg = tanhf(g2), og = sigf(g3);
        float cn = fmaf(fg, c, ig * gg);
        float hn = og * tanhf(cn);
        if (m) { c = cn; h = hn; }

        // ---- push h (bf16 hi/lo) into every peer's tile[(t+1)&1], then arrive
        if (t + 1 < T_SEQ) {
            const uint32_t p2b = (uint32_t)((t + 1) & 1);
            float v0 = __shfl_sync(0xffffffffu, h, 2 * kp_sh);
            float v1 = __shfl_sync(0xffffffffu, h, 2 * kp_sh + 1);
            uint32_t val;
            int row;
            if (lane < 16) { val = pack_bf16(v0, v1);               row = w; }
            else           { val = pack_bf16(bf_res(v0), bf_res(v1)); row = w + 8; }
            const uint32_t off =
                (p2b * 2112u + (uint32_t)(row * 132 + (int)crank * 16 + kp_sh)) * 4u;
            #pragma unroll
            for (int pe = 0; pe < 8; pe++)
                asm volatile("st.shared::cluster.b32 [%0], %1;"
                             :: "r"(peerT[pe] + off), "r"(val) : "memory");
            __syncwarp();
            if (lane < 8)
                MBAR_ARRIVE_REMOTE(peerM[lane] + p2b * 8u);
        }

        // ---- next-step g_gx prefetch (overlaps peers' pushes)
        if (LAYER == 1) {
            int tn = (t + 1 < T_SEQ) ? t + 1 : t;
            const float* gp = gx_base + (size_t)tn * NB * 1024;
            p0 = __ldg(gp);       p1 = __ldg(gp + 256);
            p2 = __ldg(gp + 512); p3 = __ldg(gp + 768);
        }

        // ---- global stores (off critical path)
        if (LAYER == 0) {
            int pos = (dir == 0) ? t : (m ? (L - 1 - t) : t);
            float val = m ? h : 0.0f;
            __nv_bfloat16 hi = __float2bfloat16(val);
            __nv_bfloat16 lo = __float2bfloat16(val - __bfloat162float(hi));
            size_t idx = ((size_t)bglob * T_SEQ + pos) * 512 + dir * 256 + uglob;
            g_h1h[idx] = hi;
            g_h1l[idx] = lo;
        } else if (dir == 1 && t == 0) {
            g_feat[bglob * 512 + 256 + uglob] = h;
        }
    }

    if (LAYER == 1 && dir == 0)
        g_feat[bglob * 512 + uglob] = h;

    // no CTA may exit while peers might still push into its SMEM
    CLUSTER_ARRIVE();
    CLUSTER_WAIT();
}

// =====================================================================
// W_ih_l1 fp32 -> bf16 hi/lo split
// =====================================================================
__global__ void __launch_bounds__(256) conv_w1(const float* __restrict__ Wih)
{
    size_t i = (size_t)blockIdx.x * 1024 + threadIdx.x * 4;
    float4 v = *reinterpret_cast<const float4*>(Wih + i);
    float vv[4] = {v.x, v.y, v.z, v.w};
    #pragma unroll
    for (int k = 0; k < 4; k++) {
        __nv_bfloat16 hi = __float2bfloat16(vv[k]);
        __nv_bfloat16 lo = __float2bfloat16(vv[k] - __bfloat162float(hi));
        g_w1h[i + k] = hi;
        g_w1l[i + k] = lo;
    }
}

// =====================================================================
// Layer-1 input projection via HMMA (unchanged, validated).
// =====================================================================
__global__ void __launch_bounds__(256) gx_mma(
    const int* __restrict__ lengths,
    const float* __restrict__ bih, const float* __restrict__ bhh)
{
    __shared__ __align__(16) uint32_t Ah[64 * 20], Al[64 * 20];
    __shared__ __align__(16) uint32_t Bh[128 * 20], Bl[128 * 20];
    __shared__ float bias_s[128];

    const int tid  = threadIdx.x;
    const int wid  = tid >> 5;
    const int lane = tid & 31;
    const int g    = lane >> 2;
    const int t4   = lane & 3;
    const int n0   = blockIdx.x * 128;
    const int t    = blockIdx.y;
    const int dir  = blockIdx.z;

    const int m0 = (wid & 1) * 32;
    const int nw = (wid >> 1) * 32;

    const int ar = tid >> 2, ac = tid & 3;
    const int br = tid >> 1, bc = tid & 1;
    if (tid < 128) bias_s[tid] = bih[dir * 1024 + n0 + tid] + bhh[dir * 1024 + n0 + tid];

    const int La = lengths[ar];
    const int teff = dir ? ((t < La) ? (La - 1 - t) : t) : t;
    const uint4* a_h = (const uint4*)(g_h1h + ((size_t)ar * T_SEQ + teff) * 512) + ac;
    const uint4* a_l = (const uint4*)(g_h1l + ((size_t)ar * T_SEQ + teff) * 512) + ac;
    const uint4* b_h = (const uint4*)(g_w1h + ((size_t)(dir * 1024 + n0 + br)) * 512) + bc * 2;
    const uint4* b_l = (const uint4*)(g_w1l + ((size_t)(dir * 1024 + n0 + br)) * 512) + bc * 2;

    float acc[2][4][4];
    #pragma unroll
    for (int i = 0; i < 2; i++)
        #pragma unroll
        for (int j = 0; j < 4; j++)
            #pragma unroll
            for (int k = 0; k < 4; k++) acc[i][j][k] = 0.0f;

    uint4 vah = __ldg(a_h), val_ = __ldg(a_l);
    uint4 vbh0 = __ldg(b_h), vbh1 = __ldg(b_h + 1);
    uint4 vbl0 = __ldg(b_l), vbl1 = __ldg(b_l + 1);

    for (int kc = 0; kc < 16; kc++) {
        *reinterpret_cast<uint4*>(&Ah[ar * 20 + ac * 4]) = vah;
        *reinterpret_cast<uint4*>(&Al[ar * 20 + ac * 4]) = val_;
        *reinterpret_cast<uint4*>(&Bh[br * 20 + bc * 8])     = vbh0;
        *reinterpret_cast<uint4*>(&Bh[br * 20 + bc * 8 + 4]) = vbh1;
        *reinterpret_cast<uint4*>(&Bl[br * 20 + bc * 8])     = vbl0;
        *reinterpret_cast<uint4*>(&Bl[br * 20 + bc * 8 + 4]) = vbl1;
        __syncthreads();

        if (kc + 1 < 16) {
            vah  = __ldg(a_h + (kc + 1) * 4);
            val_ = __ldg(a_l + (kc + 1) * 4);
            vbh0 = __ldg(b_h + (kc + 1) * 4);
            vbh1 = __ldg(b_h + (kc + 1) * 4 + 1);
            vbl0 = __ldg(b_l + (kc + 1) * 4);
            vbl1 = __ldg(b_l + (kc + 1) * 4 + 1);
        }

        #pragma unroll
        for (int pass = 0; pass < 3; pass++) {
            const uint32_t* Am = (pass == 2) ? Al : Ah;
            const uint32_t* Bm = (pass == 1) ? Bl : Bh;
            #pragma unroll
            for (int ks = 0; ks < 2; ks++) {
                uint32_t a[2][4];
                #pragma unroll
                for (int mf = 0; mf < 2; mf++) {
                    int r = m0 + mf * 16 + g;
                    a[mf][0] = Am[r * 20 + ks * 8 + t4];
                    a[mf][1] = Am[(r + 8) * 20 + ks * 8 + t4];
                    a[mf][2] = Am[r * 20 + ks * 8 + t4 + 4];
                    a[mf][3] = Am[(r + 8) * 20 + ks * 8 + t4 + 4];
                }
                #pragma unroll
                for (int nf = 0; nf < 4; nf++) {
                    int rn = nw + nf * 8 + g;
                    uint32_t b0 = Bm[rn * 20 + ks * 8 + t4];
                    uint32_t b1 = Bm[rn * 20 + ks * 8 + t4 + 4];
                    mma_bf16(acc[0][nf], a[0], b0, b1);
                    mma_bf16(acc[1][nf], a[1], b0, b1);
                }
            }
        }
        __syncthreads();
    }

    float* gxp = g_gx + ((size_t)(dir * T_SEQ + t) * NB) * 1024 + n0;
    #pragma unroll
    for (int mf = 0; mf < 2; mf++) {
        int bi = m0 + mf * 16 + g;
        #pragma unroll
        for (int nf = 0; nf < 4; nf++) {
            int nn = nw + nf * 8 + t4 * 2;
            float bv0 = bias_s[nn], bv1 = bias_s[nn + 1];
            float2 v0 = make_float2(acc[mf][nf][0] + bv0, acc[mf][nf][1] + bv1);
            float2 v1 = make_float2(acc[mf][nf][2] + bv0, acc[mf][nf][3] + bv1);
            *reinterpret_cast<float2*>(gxp + (size_t)bi * 1024 + nn)       = v0;
            *reinterpret_cast<float2*>(gxp + (size_t)(bi + 8) * 1024 + nn) = v1;
        }
    }
}

// =====================================================================
// Head
// =====================================================================
__global__ void __launch_bounds__(256) head_fc1(const float* __restrict__ fc1_w,
                                                const float* __restrict__ fc1_b)
{
    __shared__ __align__(16) float fs[512];
    int b = blockIdx.x, n = threadIdx.x;
    for (int i = n; i < 512; i += 256) fs[i] = g_feat[b * 512 + i];
    __syncthreads();
    const float4* wp = reinterpret_cast<const float4*>(fc1_w + (size_t)n * 512);
    const float4* fp = reinterpret_cast<const float4*>(fs);
    float acc = fc1_b[n];
    #pragma unroll 4
    for (int k = 0; k < 128; k++) {
        float4 w4 = __ldg(wp + k);
        float4 f4 = fp[k];
        acc += w4.x * f4.x + w4.y * f4.y + w4.z * f4.z + w4.w * f4.w;
    }
    g_y[b * 256 + n] = fmaxf(acc, 0.0f);
}

__global__ void head_bn(const float* __restrict__ gamma, const float* __restrict__ beta)
{
    int n = threadIdx.x;
    float s = 0.0f, s2 = 0.0f;
    for (int b = 0; b < 64; b++) {
        float v = g_y[b * 256 + n];
        s += v; s2 += v * v;
    }
    float mean = s * 0.015625f;
    float var  = s2 * 0.015625f - mean * mean;
    float inv  = rsqrtf(var + 1e-5f);
    float ga = gamma[n] * inv, be = beta[n];
    for (int b = 0; b < 64; b++)
        g_y[b * 256 + n] = (g_y[b * 256 + n] - mean) * ga + be;
}

__global__ void __launch_bounds__(256) head_out(const float* __restrict__ W,
                                                const float* __restrict__ bias,
                                                float* __restrict__ out)
{
    __shared__ __align__(16) float ys[256];
    int b = blockIdx.x;
    ys[threadIdx.x] = g_y[b * 256 + threadIdx.x];
    __syncthreads();
    int o = threadIdx.x;
    if (o < 196) {
        const float4* wp = reinterpret_cast<const float4*>(W + (size_t)o * 256);
        const float4* yp = reinterpret_cast<const float4*>(ys);
        float acc = bias[o];
        #pragma unroll 4
        for (int k = 0; k < 64; k++) {
            float4 w4 = __ldg(wp + k);
            float4 y4 = yp[k];
            acc += w4.x * y4.x + w4.y * y4.y + w4.z * y4.z + w4.w * y4.w;
        }
        out[(size_t)b * 196 + o] = acc;
    }
}

// =====================================================================
extern "C" void kernel_launch(void* const* d_in, const int* in_sizes, int n_in,
                              void* d_out, int out_size)
{
    const float* x       = (const float*)d_in[0];
    const int*   lengths = (const int*)  d_in[1];
    const float* Wih0    = (const float*)d_in[2];
    const float* Whh0    = (const float*)d_in[3];
    const float* bih0    = (const float*)d_in[4];
    const float* bhh0    = (const float*)d_in[5];
    const float* Wih1    = (const float*)d_in[6];
    const float* Whh1    = (const float*)d_in[7];
    const float* bih1    = (const float*)d_in[8];
    const float* bhh1    = (const float*)d_in[9];
    const float* fc1_w   = (const float*)d_in[10];
    const float* fc1_b   = (const float*)d_in[11];
    const float* gamma   = (const float*)d_in[12];
    const float* beta    = (const float*)d_in[13];
    const float* fcow    = (const float*)d_in[14];
    const float* fcob    = (const float*)d_in[15];
    float* out = (float*)d_out;

    conv_w1<<<1024, 256>>>(Wih1);
    lstm_rec<0><<<128, 256>>>(x, lengths, Wih0, Whh0, bih0, bhh0);
    gx_mma<<<dim3(8, 1024, 2), 256>>>(lengths, bih1, bhh1);
    lstm_rec<1><<<128, 256>>>(x, lengths, Wih1, Whh1, bih1, bhh1);
    head_fc1<<<64, 256>>>(fc1_w, fc1_b);
    head_bn<<<1, 256>>>(gamma, beta);
    head_out<<<64, 256>>>(fcow, fcob, out);
}

// round 9
// speedup vs baseline: 1.9985x; 1.2976x over previous
#include <cuda_runtime.h>
#include <cuda_bf16.h>
#include <cuda_fp16.h>
#include <cooperative_groups.h>
#include <cstdint>
#include <cstddef>

namespace cg = cooperative_groups;

#define HID   256
#define T_SEQ 1024
#define NB    64

// ---------------- scratch (device globals; no allocation) ----------------
__device__ __half g_h1h[(size_t)NB * T_SEQ * 512];    // layer-0 out, fp16
__device__ __half g_w1h[(size_t)2 * 1024 * 512];      // W_ih_l1 fp16
__device__ float g_gx[(size_t)2 * T_SEQ * NB * 1024]; // layer-1 projected gates
__device__ float g_feat[NB * 512];
__device__ float g_y[NB * 256];

__device__ __forceinline__ float sigf(float x) {
    return __fdividef(1.0f, 1.0f + __expf(-x));
}
// fast tanh: 1 - 2/(e^{2x}+1); saturates correctly at +-1 for large |x|
__device__ __forceinline__ float tanh_fast(float x) {
    float e = __expf(2.0f * x);
    return 1.0f - __fdividef(2.0f, e + 1.0f);
}

// mma.sync m16n8k16 row.col fp16 -> f32 (same fragment layout as bf16, validated)
__device__ __forceinline__ void mma_f16(float* c, const uint32_t* a,
                                        uint32_t b0, uint32_t b1) {
    asm volatile(
        "mma.sync.aligned.m16n8k16.row.col.f32.f16.f16.f32 "
        "{%0,%1,%2,%3}, {%4,%5,%6,%7}, {%8,%9}, {%0,%1,%2,%3};"
        : "+f"(c[0]), "+f"(c[1]), "+f"(c[2]), "+f"(c[3])
        : "r"(a[0]), "r"(a[1]), "r"(a[2]), "r"(a[3]), "r"(b0), "r"(b1));
}

__device__ __forceinline__ void ldsm4(uint32_t* r, uint32_t addr) {
    asm volatile(
        "ldmatrix.sync.aligned.m8n8.x4.shared.b16 {%0,%1,%2,%3}, [%4];"
        : "=r"(r[0]), "=r"(r[1]), "=r"(r[2]), "=r"(r[3]) : "r"(addr));
}

__device__ __forceinline__ uint32_t smem_u32(const void* p) {
    uint32_t a;
    asm("{ .reg .u64 t; cvta.to.shared.u64 t, %1; cvt.u32.u64 %0, t; }" : "=r"(a) : "l"(p));
    return a;
}

__device__ __forceinline__ uint32_t pack_f16(float a, float b) {
    __half2 v = __floats2half2_rn(a, b);
    return *reinterpret_cast<uint32_t*>(&v);
}
__device__ __forceinline__ float f16_res(float x) {
    return x - __half2float(__float2half_rn(x));
}

#define MBAR_INIT(a, c) \
    asm volatile("mbarrier.init.shared.b64 [%0], %1;" :: "r"(a), "r"((uint32_t)(c)) : "memory")

#define MBAR_WAIT_CL(a, par) do {                                                   \
    uint32_t _m = (a), _p = (par);                                                  \
    asm volatile("{\n\t.reg .pred P1;\n\t"                                          \
        "WLC_%=:\n\t"                                                               \
        "mbarrier.try_wait.parity.acquire.cluster.shared::cta.b64 P1, [%0], %1;\n\t"\
        "@P1 bra.uni WDC_%=;\n\t"                                                   \
        "bra.uni WLC_%=;\n\t"                                                       \
        "WDC_%=:\n\t}" :: "r"(_m), "r"(_p) : "memory");                             \
} while (0)

#define MBAR_ARRIVE_REMOTE(a) \
    asm volatile("mbarrier.arrive.release.cluster.shared::cluster.b64 _, [%0];" \
                 :: "r"(a) : "memory")

#define CLUSTER_ARRIVE() asm volatile("barrier.cluster.arrive.aligned;" ::: "memory")
#define CLUSTER_WAIT()   asm volatile("barrier.cluster.wait.aligned;" ::: "memory")

// =====================================================================
// Recurrent LSTM on tensor cores (fp16 single-W-pass).
// A tile M=16: rows 0-7 h_hi(fp16), rows 8-15 h_lo(fp16 residual).
// One pass x W_fp16 captures h_hi*W + h_lo*W (drops only W residual).
// 32 HMMA/warp/step. Push-based mbarrier exchange (validated R8).
// =====================================================================
template<int LAYER>
__global__ void __launch_bounds__(256, 1) __cluster_dims__(8, 1, 1)
lstm_rec(const float* __restrict__ x, const int* __restrict__ lengths,
         const float* __restrict__ Wih, const float* __restrict__ Whh,
         const float* __restrict__ bih, const float* __restrict__ bhh)
{
    __shared__ __align__(16) uint32_t Ahl[2][16 * 132];  // double-buffered A tiles
    __shared__ __align__(16) float gates_s[8 * 132];     // [b][r_local]
    __shared__ __align__(8)  uint64_t mbars[2];

    const int tid   = threadIdx.x;
    const int w     = tid >> 5;
    const int lane  = tid & 31;
    const int g     = lane >> 2;
    const int t4    = lane & 3;
    uint32_t crank;
    asm("mov.u32 %0, %%cluster_ctarank;" : "=r"(crank));
    const int group = blockIdx.x >> 3;
    const int dir   = group >> 3;
    const int bg    = group & 7;
    const int b_upd = w;
    const int u     = lane;
    const int uglob = (int)crank * 32 + u;
    const int bglob = bg * 8 + b_upd;
    const int L     = lengths[bglob];

    // ---- W_hh fragments (fp16) into registers: wf[ks][j][slot]
    uint32_t wf[16][2][2];
    #pragma unroll
    for (int j = 0; j < 2; j++) {
        int rl   = w * 16 + j * 8 + g;
        int grow = dir * 1024 + ((rl >> 5) << 8) + (int)crank * 32 + (rl & 31);
        const float* wp = Whh + (size_t)grow * 256;
        #pragma unroll
        for (int ks = 0; ks < 16; ks++) {
            #pragma unroll
            for (int s = 0; s < 2; s++) {
                int kp = ks * 8 + t4 + s * 4;
                float2 wv = *reinterpret_cast<const float2*>(wp + kp * 2);
                wf[ks][j][s] = pack_f16(wv.x, wv.y);
            }
        }
    }

    // ---- layer-0 input projection params (IN = 3)
    float wia[4], wib[4], wic[4], bs4[4];
    if (LAYER == 0) {
        #pragma unroll
        for (int q = 0; q < 4; q++) {
            int row = dir * 1024 + q * 256 + uglob;
            wia[q] = Wih[(size_t)row * 3 + 0];
            wib[q] = Wih[(size_t)row * 3 + 1];
            wic[q] = Wih[(size_t)row * 3 + 2];
            bs4[q] = bih[row] + bhh[row];
        }
    }

    for (int i = tid; i < 2 * 16 * 132; i += 256) ((uint32_t*)Ahl)[i] = 0u;
    const uint32_t mbase = smem_u32(mbars);
    if (tid == 0) {
        MBAR_INIT(mbase, 64);
        MBAR_INIT(mbase + 8, 64);
        asm volatile("fence.mbarrier_init.release.cluster;" ::: "memory");
    }
    __syncthreads();
    CLUSTER_ARRIVE();
    CLUSTER_WAIT();

    // ---- peer addresses
    const uint32_t tbase = smem_u32(Ahl);
    uint32_t peerT[8], peerM[8];
    #pragma unroll
    for (int pe = 0; pe < 8; pe++) {
        asm("mapa.shared::cluster.u32 %0, %1, %2;" : "=r"(peerT[pe]) : "r"(tbase), "r"(pe));
        asm("mapa.shared::cluster.u32 %0, %1, %2;" : "=r"(peerM[pe]) : "r"(mbase), "r"(pe));
    }

    const int lrow  = lane & 15;
    const int lcoff = (lane >> 4) * 4;
    const uint32_t aB0 = tbase + (uint32_t)(lrow * 132 + lcoff) * 4u;
    const uint32_t aB1 = aB0 + 2112u * 4u;

    const float* gx_base = g_gx + ((size_t)dir * T_SEQ * NB + bglob) * 1024 + uglob;
    const int kp_sh = lane & 15;

    float c = 0.0f, h = 0.0f;
    int ph0 = 0, ph1 = 0;

    float p0, p1, p2, p3;
    if (LAYER == 1) {
        const float* gp = gx_base;
        p0 = __ldg(gp);       p1 = __ldg(gp + 256);
        p2 = __ldg(gp + 512); p3 = __ldg(gp + 768);
    }

    for (int t = 0; t < T_SEQ; t++) {
        const bool m = (t < L);

        if (LAYER == 0) {
            int teff = (dir == 0) ? t : (m ? (L - 1 - t) : t);
            const float* xp = x + ((size_t)bglob * T_SEQ + teff) * 3;
            float x0 = xp[0], x1 = xp[1], x2 = xp[2];
            p0 = bs4[0] + wia[0] * x0 + wib[0] * x1 + wic[0] * x2;
            p1 = bs4[1] + wia[1] * x0 + wib[1] * x1 + wic[1] * x2;
            p2 = bs4[2] + wia[2] * x0 + wib[2] * x1 + wic[2] * x2;
            p3 = bs4[3] + wia[3] * x0 + wib[3] * x1 + wic[3] * x2;
        }

        // ---- wait for this step's A tile (t=0 reads zeros)
        if (t > 0) {
            if (t & 1) { MBAR_WAIT_CL(mbase + 8, ph1); ph1 ^= 1; }
            else       { MBAR_WAIT_CL(mbase,     ph0); ph0 ^= 1; }
        }
        const uint32_t aBase = (t & 1) ? aB1 : aB0;

        // ---- recurrent matvec: 1 fp16 pass, 2 independent chains (j=0,1)
        float acc0[4] = {0.f, 0.f, 0.f, 0.f};
        float acc1[4] = {0.f, 0.f, 0.f, 0.f};
        #pragma unroll
        for (int ks = 0; ks < 16; ks++) {
            uint32_t a[4];
            ldsm4(a, aBase + (uint32_t)ks * 32u);
            mma_f16(acc0, a, wf[ks][0][0], wf[ks][0][1]);
            mma_f16(acc1, a, wf[ks][1][0], wf[ks][1][1]);
        }

        // ---- dump gates: c[0,1] = hi rows (g), c[2,3] = lo rows (g+8); sum them
        *reinterpret_cast<float2*>(&gates_s[g * 132 + w * 16 + 2 * t4]) =
            make_float2(acc0[0] + acc0[2], acc0[1] + acc0[3]);
        *reinterpret_cast<float2*>(&gates_s[g * 132 + w * 16 + 8 + 2 * t4]) =
            make_float2(acc1[0] + acc1[2], acc1[1] + acc1[3]);
        __syncthreads();

        // ---- gate nonlinearity + state update: thread (b_upd, u)
        float g0 = p0 + gates_s[b_upd * 132 + u];
        float g1 = p1 + gates_s[b_upd * 132 + 32 + u];
        float g2 = p2 + gates_s[b_upd * 132 + 64 + u];
        float g3 = p3 + gates_s[b_upd * 132 + 96 + u];
        float ig = sigf(g0), fg = sigf(g1);
        float gg = tanh_fast(g2), og = sigf(g3);
        float cn = fmaf(fg, c, ig * gg);
        float hn = og * tanh_fast(cn);
        if (m) { c = cn; h = hn; }

        // ---- push h (fp16 hi/lo) into every peer's tile[(t+1)&1], then arrive
        if (t + 1 < T_SEQ) {
            const uint32_t p2b = (uint32_t)((t + 1) & 1);
            float v0 = __shfl_sync(0xffffffffu, h, 2 * kp_sh);
            float v1 = __shfl_sync(0xffffffffu, h, 2 * kp_sh + 1);
            uint32_t val;
            int row;
            if (lane < 16) { val = pack_f16(v0, v1);                 row = w; }
            else           { val = pack_f16(f16_res(v0), f16_res(v1)); row = w + 8; }
            const uint32_t off =
                (p2b * 2112u + (uint32_t)(row * 132 + (int)crank * 16 + kp_sh)) * 4u;
            #pragma unroll
            for (int pe = 0; pe < 8; pe++)
                asm volatile("st.shared::cluster.b32 [%0], %1;"
                             :: "r"(peerT[pe] + off), "r"(val) : "memory");
            __syncwarp();
            if (lane < 8)
                MBAR_ARRIVE_REMOTE(peerM[lane] + p2b * 8u);
        }

        // ---- next-step g_gx prefetch (overlaps peers' pushes)
        if (LAYER == 1) {
            int tn = (t + 1 < T_SEQ) ? t + 1 : t;
            const float* gp = gx_base + (size_t)tn * NB * 1024;
            p0 = __ldg(gp);       p1 = __ldg(gp + 256);
            p2 = __ldg(gp + 512); p3 = __ldg(gp + 768);
        }

        // ---- global stores (off critical path)
        if (LAYER == 0) {
            int pos = (dir == 0) ? t : (m ? (L - 1 - t) : t);
            float val = m ? h : 0.0f;
            g_h1h[((size_t)bglob * T_SEQ + pos) * 512 + dir * 256 + uglob] =
                __float2half_rn(val);
        } else if (dir == 1 && t == 0) {
            g_feat[bglob * 512 + 256 + uglob] = h;
        }
    }

    if (LAYER == 1 && dir == 0)
        g_feat[bglob * 512 + uglob] = h;

    CLUSTER_ARRIVE();
    CLUSTER_WAIT();
}

// =====================================================================
// W_ih_l1 fp32 -> fp16
// =====================================================================
__global__ void __launch_bounds__(256) conv_w1(const float* __restrict__ Wih)
{
    size_t i = (size_t)blockIdx.x * 1024 + threadIdx.x * 4;
    float4 v = *reinterpret_cast<const float4*>(Wih + i);
    g_w1h[i + 0] = __float2half_rn(v.x);
    g_w1h[i + 1] = __float2half_rn(v.y);
    g_w1h[i + 2] = __float2half_rn(v.z);
    g_w1h[i + 3] = __float2half_rn(v.w);
}

// =====================================================================
// Layer-1 input projection via fp16 HMMA, single pass.
// CTA tile: M=64 (batch), N=128, K=512 in 16 chunks of 32.
// 8 warps 2(m) x 4(n); 256 HMMA/warp total.
// =====================================================================
__global__ void __launch_bounds__(256) gx_mma(
    const int* __restrict__ lengths,
    const float* __restrict__ bih, const float* __restrict__ bhh)
{
    __shared__ __align__(16) uint32_t Ax[64 * 20];
    __shared__ __align__(16) uint32_t Bx[128 * 20];
    __shared__ float bias_s[128];

    const int tid  = threadIdx.x;
    const int wid  = tid >> 5;
    const int lane = tid & 31;
    const int g    = lane >> 2;
    const int t4   = lane & 3;
    const int n0   = blockIdx.x * 128;
    const int t    = blockIdx.y;
    const int dir  = blockIdx.z;

    const int m0 = (wid & 1) * 32;
    const int nw = (wid >> 1) * 32;

    const int ar = tid >> 2, ac = tid & 3;       // A: row ar, quad ac
    const int br = tid >> 1, bc = tid & 1;       // B: row br, half bc
    if (tid < 128) bias_s[tid] = bih[dir * 1024 + n0 + tid] + bhh[dir * 1024 + n0 + tid];

    const int La = lengths[ar];
    const int teff = dir ? ((t < La) ? (La - 1 - t) : t) : t;
    const uint4* a_p = (const uint4*)(g_h1h + ((size_t)ar * T_SEQ + teff) * 512) + ac;
    const uint4* b_p = (const uint4*)(g_w1h + ((size_t)(dir * 1024 + n0 + br)) * 512) + bc * 2;

    float acc[2][4][4];
    #pragma unroll
    for (int i = 0; i < 2; i++)
        #pragma unroll
        for (int j = 0; j < 4; j++)
            #pragma unroll
            for (int k = 0; k < 4; k++) acc[i][j][k] = 0.0f;

    uint4 va  = __ldg(a_p);
    uint4 vb0 = __ldg(b_p), vb1 = __ldg(b_p + 1);

    for (int kc = 0; kc < 16; kc++) {
        *reinterpret_cast<uint4*>(&Ax[ar * 20 + ac * 4]) = va;
        *reinterpret_cast<uint4*>(&Bx[br * 20 + bc * 8])     = vb0;
        *reinterpret_cast<uint4*>(&Bx[br * 20 + bc * 8 + 4]) = vb1;
        __syncthreads();

        if (kc + 1 < 16) {
            va  = __ldg(a_p + (kc + 1) * 4);
            vb0 = __ldg(b_p + (kc + 1) * 4);
            vb1 = __ldg(b_p + (kc + 1) * 4 + 1);
        }

        #pragma unroll
        for (int ks = 0; ks < 2; ks++) {
            uint32_t a[2][4];
            #pragma unroll
            for (int mf = 0; mf < 2; mf++) {
                int r = m0 + mf * 16 + g;
                a[mf][0] = Ax[r * 20 + ks * 8 + t4];
                a[mf][1] = Ax[(r + 8) * 20 + ks * 8 + t4];
                a[mf][2] = Ax[r * 20 + ks * 8 + t4 + 4];
                a[mf][3] = Ax[(r + 8) * 20 + ks * 8 + t4 + 4];
            }
            #pragma unroll
            for (int nf = 0; nf < 4; nf++) {
                int rn = nw + nf * 8 + g;
                uint32_t b0 = Bx[rn * 20 + ks * 8 + t4];
                uint32_t b1 = Bx[rn * 20 + ks * 8 + t4 + 4];
                mma_f16(acc[0][nf], a[0], b0, b1);
                mma_f16(acc[1][nf], a[1], b0, b1);
            }
        }
        __syncthreads();
    }

    float* gxp = g_gx + ((size_t)(dir * T_SEQ + t) * NB) * 1024 + n0;
    #pragma unroll
    for (int mf = 0; mf < 2; mf++) {
        int bi = m0 + mf * 16 + g;
        #pragma unroll
        for (int nf = 0; nf < 4; nf++) {
            int nn = nw + nf * 8 + t4 * 2;
            float bv0 = bias_s[nn], bv1 = bias_s[nn + 1];
            float2 v0 = make_float2(acc[mf][nf][0] + bv0, acc[mf][nf][1] + bv1);
            float2 v1 = make_float2(acc[mf][nf][2] + bv0, acc[mf][nf][3] + bv1);
            *reinterpret_cast<float2*>(gxp + (size_t)bi * 1024 + nn)       = v0;
            *reinterpret_cast<float2*>(gxp + (size_t)(bi + 8) * 1024 + nn) = v1;
        }
    }
}

// =====================================================================
// Head
// =====================================================================
__global__ void __launch_bounds__(256) head_fc1(const float* __restrict__ fc1_w,
                                                const float* __restrict__ fc1_b)
{
    __shared__ __align__(16) float fs[512];
    int b = blockIdx.x, n = threadIdx.x;
    for (int i = n; i < 512; i += 256) fs[i] = g_feat[b * 512 + i];
    __syncthreads();
    const float4* wp = reinterpret_cast<const float4*>(fc1_w + (size_t)n * 512);
    const float4* fp = reinterpret_cast<const float4*>(fs);
    float acc = fc1_b[n];
    #pragma unroll 4
    for (int k = 0; k < 128; k++) {
        float4 w4 = __ldg(wp + k);
        float4 f4 = fp[k];
        acc += w4.x * f4.x + w4.y * f4.y + w4.z * f4.z + w4.w * f4.w;
    }
    g_y[b * 256 + n] = fmaxf(acc, 0.0f);
}

__global__ void head_bn(const float* __restrict__ gamma, const float* __restrict__ beta)
{
    int n = threadIdx.x;
    float s = 0.0f, s2 = 0.0f;
    for (int b = 0; b < 64; b++) {
        float v = g_y[b * 256 + n];
        s += v; s2 += v * v;
    }
    float mean = s * 0.015625f;
    float var  = s2 * 0.015625f - mean * mean;
    float inv  = rsqrtf(var + 1e-5f);
    float ga = gamma[n] * inv, be = beta[n];
    for (int b = 0; b < 64; b++)
        g_y[b * 256 + n] = (g_y[b * 256 + n] - mean) * ga + be;
}

__global__ void __launch_bounds__(256) head_out(const float* __restrict__ W,
                                                const float* __restrict__ bias,
                                                float* __restrict__ out)
{
    __shared__ __align__(16) float ys[256];
    int b = blockIdx.x;
    ys[threadIdx.x] = g_y[b * 256 + threadIdx.x];
    __syncthreads();
    int o = threadIdx.x;
    if (o < 196) {
        const float4* wp = reinterpret_cast<const float4*>(W + (size_t)o * 256);
        const float4* yp = reinterpret_cast<const float4*>(ys);
        float acc = bias[o];
        #pragma unroll 4
        for (int k = 0; k < 64; k++) {
            float4 w4 = __ldg(wp + k);
            float4 y4 = yp[k];
            acc += w4.x * y4.x + w4.y * y4.y + w4.z * y4.z + w4.w * y4.w;
        }
        out[(size_t)b * 196 + o] = acc;
    }
}

// =====================================================================
extern "C" void kernel_launch(void* const* d_in, const int* in_sizes, int n_in,
                              void* d_out, int out_size)
{
    const float* x       = (const float*)d_in[0];
    const int*   lengths = (const int*)  d_in[1];
    const float* Wih0    = (const float*)d_in[2];
    const float* Whh0    = (const float*)d_in[3];
    const float* bih0    = (const float*)d_in[4];
    const float* bhh0    = (const float*)d_in[5];
    const float* Wih1    = (const float*)d_in[6];
    const float* Whh1    = (const float*)d_in[7];
    const float* bih1    = (const float*)d_in[8];
    const float* bhh1    = (const float*)d_in[9];
    const float* fc1_w   = (const float*)d_in[10];
    const float* fc1_b   = (const float*)d_in[11];
    const float* gamma   = (const float*)d_in[12];
    const float* beta    = (const float*)d_in[13];
    const float* fcow    = (const float*)d_in[14];
    const float* fcob    = (const float*)d_in[15];
    float* out = (float*)d_out;

    conv_w1<<<1024, 256>>>(Wih1);
    lstm_rec<0><<<128, 256>>>(x, lengths, Wih0, Whh0, bih0, bhh0);
    gx_mma<<<dim3(8, 1024, 2), 256>>>(lengths, bih1, bhh1);
    lstm_rec<1><<<128, 256>>>(x, lengths, Wih1, Whh1, bih1, bhh1);
    head_fc1<<<64, 256>>>(fc1_w, fc1_b);
    head_bn<<<1, 256>>>(gamma, beta);
    head_out<<<64, 256>>>(fcow, fcob, out);
}

// round 10
// speedup vs baseline: 2.0296x; 1.0155x over previous
#include <cuda_runtime.h>
#include <cuda_bf16.h>
#include <cuda_fp16.h>
#include <cooperative_groups.h>
#include <cstdint>
#include <cstddef>

namespace cg = cooperative_groups;

#define HID   256
#define T_SEQ 1024
#define NB    64

// ---------------- scratch (device globals; no allocation) ----------------
__device__ __half g_h1h[(size_t)NB * T_SEQ * 512];    // layer-0 out, fp16
__device__ __half g_w1h[(size_t)2 * 1024 * 512];      // W_ih_l1 fp16
__device__ float g_gx[(size_t)2 * T_SEQ * NB * 1024]; // layer-1 projected gates
__device__ float g_feat[NB * 512];
__device__ float g_y[NB * 256];

__device__ __forceinline__ float sigf(float x) {
    return __fdividef(1.0f, 1.0f + __expf(-x));
}
__device__ __forceinline__ float tanh_fast(float x) {
    float e = __expf(2.0f * x);
    return 1.0f - __fdividef(2.0f, e + 1.0f);
}

// mma.sync m16n8k16 row.col fp16 -> f32 (validated fragment layout)
__device__ __forceinline__ void mma_f16(float* c, const uint32_t* a,
                                        uint32_t b0, uint32_t b1) {
    asm volatile(
        "mma.sync.aligned.m16n8k16.row.col.f32.f16.f16.f32 "
        "{%0,%1,%2,%3}, {%4,%5,%6,%7}, {%8,%9}, {%0,%1,%2,%3};"
        : "+f"(c[0]), "+f"(c[1]), "+f"(c[2]), "+f"(c[3])
        : "r"(a[0]), "r"(a[1]), "r"(a[2]), "r"(a[3]), "r"(b0), "r"(b1));
}

__device__ __forceinline__ void ldsm4(uint32_t* r, uint32_t addr) {
    asm volatile(
        "ldmatrix.sync.aligned.m8n8.x4.shared.b16 {%0,%1,%2,%3}, [%4];"
        : "=r"(r[0]), "=r"(r[1]), "=r"(r[2]), "=r"(r[3]) : "r"(addr));
}

__device__ __forceinline__ uint32_t smem_u32(const void* p) {
    uint32_t a;
    asm("{ .reg .u64 t; cvta.to.shared.u64 t, %1; cvt.u32.u64 %0, t; }" : "=r"(a) : "l"(p));
    return a;
}

__device__ __forceinline__ uint32_t pack_f16(float a, float b) {
    __half2 v = __floats2half2_rn(a, b);
    return *reinterpret_cast<uint32_t*>(&v);
}
__device__ __forceinline__ float f16_res(float x) {
    return x - __half2float(__float2half_rn(x));
}

#define MBAR_INIT(a, c) \
    asm volatile("mbarrier.init.shared.b64 [%0], %1;" :: "r"(a), "r"((uint32_t)(c)) : "memory")

#define MBAR_WAIT_CL(a, par) do {                                                   \
    uint32_t _m = (a), _p = (par);                                                  \
    asm volatile("{\n\t.reg .pred P1;\n\t"                                          \
        "WLC_%=:\n\t"                                                               \
        "mbarrier.try_wait.parity.acquire.cluster.shared::cta.b64 P1, [%0], %1;\n\t"\
        "@P1 bra.uni WDC_%=;\n\t"                                                   \
        "bra.uni WLC_%=;\n\t"                                                       \
        "WDC_%=:\n\t}" :: "r"(_m), "r"(_p) : "memory");                             \
} while (0)

#define MBAR_ARRIVE_REMOTE(a) \
    asm volatile("mbarrier.arrive.release.cluster.shared::cluster.b64 _, [%0];" \
                 :: "r"(a) : "memory")

#define CLUSTER_ARRIVE() asm volatile("barrier.cluster.arrive.aligned;" ::: "memory")
#define CLUSTER_WAIT()   asm volatile("barrier.cluster.wait.aligned;" ::: "memory")

// =====================================================================
// Recurrent LSTM, BOTH directions interleaved in one CTA (stream
// pipelining: dir-1 compute hides dir-0 exchange latency and vice versa).
// Cluster of 8 CTAs = one batch-group of 8. Per dir: A tile M=16
// (rows 0-7 h_hi fp16, 8-15 h_lo residual), single W fp16 pass,
// 32 HMMA/warp/step/dir, push-based mbarrier exchange (validated R8/R9).
// =====================================================================
template<int LAYER>
__global__ void __launch_bounds__(256, 1) __cluster_dims__(8, 1, 1)
lstm_rec(const float* __restrict__ x, const int* __restrict__ lengths,
         const float* __restrict__ Wih, const float* __restrict__ Whh,
         const float* __restrict__ bih, const float* __restrict__ bhh)
{
    __shared__ __align__(16) uint32_t Ahl[4 * 2112];   // [dir][buf][16*132]
    __shared__ __align__(16) float gates_s[2][8 * 132];
    __shared__ __align__(8)  uint64_t mbars[4];        // [dir][buf]

    const int tid   = threadIdx.x;
    const int w     = tid >> 5;
    const int lane  = tid & 31;
    const int g     = lane >> 2;
    const int t4    = lane & 3;
    uint32_t crank;
    asm("mov.u32 %0, %%cluster_ctarank;" : "=r"(crank));
    const int bg    = blockIdx.x >> 3;
    const int b_upd = w;
    const int u     = lane;
    const int uglob = (int)crank * 32 + u;
    const int bglob = bg * 8 + b_upd;
    const int L     = lengths[bglob];

    // ---- W_hh fragments (fp16) for BOTH dirs: wf[d][ks][j][slot]
    uint32_t wf[2][16][2][2];
    #pragma unroll
    for (int d = 0; d < 2; d++) {
        #pragma unroll
        for (int j = 0; j < 2; j++) {
            int rl   = w * 16 + j * 8 + g;
            int grow = d * 1024 + ((rl >> 5) << 8) + (int)crank * 32 + (rl & 31);
            const float* wp = Whh + (size_t)grow * 256;
            #pragma unroll
            for (int ks = 0; ks < 16; ks++) {
                #pragma unroll
                for (int s = 0; s < 2; s++) {
                    int kp = ks * 8 + t4 + s * 4;
                    float2 wv = *reinterpret_cast<const float2*>(wp + kp * 2);
                    wf[d][ks][j][s] = pack_f16(wv.x, wv.y);
                }
            }
        }
    }

    // ---- layer-0 input projection params (IN = 3), both dirs
    float wia[2][4], wib[2][4], wic[2][4], bs4[2][4];
    if (LAYER == 0) {
        #pragma unroll
        for (int d = 0; d < 2; d++)
            #pragma unroll
            for (int q = 0; q < 4; q++) {
                int row = d * 1024 + q * 256 + uglob;
                wia[d][q] = Wih[(size_t)row * 3 + 0];
                wib[d][q] = Wih[(size_t)row * 3 + 1];
                wic[d][q] = Wih[(size_t)row * 3 + 2];
                bs4[d][q] = bih[row] + bhh[row];
            }
    }

    for (int i = tid; i < 4 * 2112; i += 256) Ahl[i] = 0u;
    const uint32_t mbase = smem_u32(mbars);
    if (tid == 0) {
        #pragma unroll
        for (int i = 0; i < 4; i++) MBAR_INIT(mbase + i * 8, 64);
        asm volatile("fence.mbarrier_init.release.cluster;" ::: "memory");
    }
    __syncthreads();
    CLUSTER_ARRIVE();
    CLUSTER_WAIT();

    // ---- peer addresses
    const uint32_t tbase = smem_u32(Ahl);
    uint32_t peerT[8], peerM[8];
    #pragma unroll
    for (int pe = 0; pe < 8; pe++) {
        asm("mapa.shared::cluster.u32 %0, %1, %2;" : "=r"(peerT[pe]) : "r"(tbase), "r"(pe));
        asm("mapa.shared::cluster.u32 %0, %1, %2;" : "=r"(peerM[pe]) : "r"(mbase), "r"(pe));
    }

    const int lrow  = lane & 15;
    const int lcoff = (lane >> 4) * 4;
    // ldsm bases: [dir][buf]
    uint32_t aB[2][2];
    #pragma unroll
    for (int d = 0; d < 2; d++)
        #pragma unroll
        for (int pb = 0; pb < 2; pb++)
            aB[d][pb] = tbase + (uint32_t)((d * 2 + pb) * 2112 + lrow * 132 + lcoff) * 4u;

    const float* gx_b0 = g_gx + ((size_t)0 * T_SEQ * NB + bglob) * 1024 + uglob;
    const float* gx_b1 = g_gx + ((size_t)1 * T_SEQ * NB + bglob) * 1024 + uglob;
    const int kp_sh = lane & 15;

    float cst[2] = {0.0f, 0.0f}, hst[2] = {0.0f, 0.0f};
    int ph[2][2] = {{0, 0}, {0, 0}};
    float p[2][4];

    if (LAYER == 1) {
        p[0][0] = __ldg(gx_b0);       p[0][1] = __ldg(gx_b0 + 256);
        p[0][2] = __ldg(gx_b0 + 512); p[0][3] = __ldg(gx_b0 + 768);
        p[1][0] = __ldg(gx_b1);       p[1][1] = __ldg(gx_b1 + 256);
        p[1][2] = __ldg(gx_b1 + 512); p[1][3] = __ldg(gx_b1 + 768);
    }

    for (int t = 0; t < T_SEQ; t++) {
        const bool m = (t < L);
        const int buf = t & 1;
        const uint32_t nbuf = (uint32_t)((t + 1) & 1);

        #pragma unroll
        for (int d = 0; d < 2; d++) {
            // ---- layer-0 input projection (L2-resident x; hidden by MMA)
            if (LAYER == 0) {
                int teff = (d == 0) ? t : (m ? (L - 1 - t) : t);
                const float* xp = x + ((size_t)bglob * T_SEQ + teff) * 3;
                float x0 = xp[0], x1 = xp[1], x2 = xp[2];
                p[d][0] = bs4[d][0] + wia[d][0] * x0 + wib[d][0] * x1 + wic[d][0] * x2;
                p[d][1] = bs4[d][1] + wia[d][1] * x0 + wib[d][1] * x1 + wic[d][1] * x2;
                p[d][2] = bs4[d][2] + wia[d][2] * x0 + wib[d][2] * x1 + wic[d][2] * x2;
                p[d][3] = bs4[d][3] + wia[d][3] * x0 + wib[d][3] * x1 + wic[d][3] * x2;
            }

            // ---- wait for this dir's A tile (t=0 reads zeros)
            if (t > 0) {
                MBAR_WAIT_CL(mbase + (uint32_t)(d * 2 + buf) * 8u, ph[d][buf]);
                ph[d][buf] ^= 1;
            }
            const uint32_t aBase = aB[d][buf];

            // ---- matvec: 1 fp16 pass, 2 independent chains (j=0,1)
            float acc0[4] = {0.f, 0.f, 0.f, 0.f};
            float acc1[4] = {0.f, 0.f, 0.f, 0.f};
            #pragma unroll
            for (int ks = 0; ks < 16; ks++) {
                uint32_t a[4];
                ldsm4(a, aBase + (uint32_t)ks * 32u);
                mma_f16(acc0, a, wf[d][ks][0][0], wf[d][ks][0][1]);
                mma_f16(acc1, a, wf[d][ks][1][0], wf[d][ks][1][1]);
            }

            // ---- dump gates (hi rows + lo rows summed)
            *reinterpret_cast<float2*>(&gates_s[d][g * 132 + w * 16 + 2 * t4]) =
                make_float2(acc0[0] + acc0[2], acc0[1] + acc0[3]);
            *reinterpret_cast<float2*>(&gates_s[d][g * 132 + w * 16 + 8 + 2 * t4]) =
                make_float2(acc1[0] + acc1[2], acc1[1] + acc1[3]);
            __syncthreads();

            // ---- gate nonlinearity + state update: thread (b_upd, u)
            float g0 = p[d][0] + gates_s[d][b_upd * 132 + u];
            float g1 = p[d][1] + gates_s[d][b_upd * 132 + 32 + u];
            float g2 = p[d][2] + gates_s[d][b_upd * 132 + 64 + u];
            float g3 = p[d][3] + gates_s[d][b_upd * 132 + 96 + u];
            float ig = sigf(g0), fg = sigf(g1);
            float gg = tanh_fast(g2), og = sigf(g3);
            float cn = fmaf(fg, cst[d], ig * gg);
            float hn = og * tanh_fast(cn);
            if (m) { cst[d] = cn; hst[d] = hn; }

            // ---- push h (fp16 hi/lo) into every peer's tile[d][nbuf], arrive
            if (t + 1 < T_SEQ) {
                float hh = hst[d];
                float v0 = __shfl_sync(0xffffffffu, hh, 2 * kp_sh);
                float v1 = __shfl_sync(0xffffffffu, hh, 2 * kp_sh + 1);
                uint32_t val;
                int row;
                if (lane < 16) { val = pack_f16(v0, v1);                 row = w; }
                else           { val = pack_f16(f16_res(v0), f16_res(v1)); row = w + 8; }
                const uint32_t off =
                    (uint32_t)((d * 2 + (int)nbuf) * 2112 +
                               row * 132 + (int)crank * 16 + kp_sh) * 4u;
                #pragma unroll
                for (int pe = 0; pe < 8; pe++)
                    asm volatile("st.shared::cluster.b32 [%0], %1;"
                                 :: "r"(peerT[pe] + off), "r"(val) : "memory");
                __syncwarp();
                if (lane < 8)
                    MBAR_ARRIVE_REMOTE(peerM[lane] + (uint32_t)(d * 2 + (int)nbuf) * 8u);
            }

            // ---- next-step g_gx prefetch for this dir (long cover)
            if (LAYER == 1) {
                int tn = (t + 1 < T_SEQ) ? t + 1 : t;
                const float* gp = (d == 0 ? gx_b0 : gx_b1) + (size_t)tn * NB * 1024;
                p[d][0] = __ldg(gp);       p[d][1] = __ldg(gp + 256);
                p[d][2] = __ldg(gp + 512); p[d][3] = __ldg(gp + 768);
            }

            // ---- global stores (off critical path)
            if (LAYER == 0) {
                int pos = (d == 0) ? t : (m ? (L - 1 - t) : t);
                float val = m ? hst[d] : 0.0f;
                g_h1h[((size_t)bglob * T_SEQ + pos) * 512 + d * 256 + uglob] =
                    __float2half_rn(val);
            } else if (d == 1 && t == 0) {
                g_feat[bglob * 512 + 256 + uglob] = hst[1];
            }
        }
    }

    if (LAYER == 1)
        g_feat[bglob * 512 + uglob] = hst[0];

    CLUSTER_ARRIVE();
    CLUSTER_WAIT();
}

// =====================================================================
// W_ih_l1 fp32 -> fp16
// =====================================================================
__global__ void __launch_bounds__(256) conv_w1(const float* __restrict__ Wih)
{
    size_t i = (size_t)blockIdx.x * 1024 + threadIdx.x * 4;
    float4 v = *reinterpret_cast<const float4*>(Wih + i);
    g_w1h[i + 0] = __float2half_rn(v.x);
    g_w1h[i + 1] = __float2half_rn(v.y);
    g_w1h[i + 2] = __float2half_rn(v.z);
    g_w1h[i + 3] = __float2half_rn(v.w);
}

// =====================================================================
// Layer-1 input projection via fp16 HMMA (unchanged, validated).
// =====================================================================
__global__ void __launch_bounds__(256) gx_mma(
    const int* __restrict__ lengths,
    const float* __restrict__ bih, const float* __restrict__ bhh)
{
    __shared__ __align__(16) uint32_t Ax[64 * 20];
    __shared__ __align__(16) uint32_t Bx[128 * 20];
    __shared__ float bias_s[128];

    const int tid  = threadIdx.x;
    const int wid  = tid >> 5;
    const int lane = tid & 31;
    const int g    = lane >> 2;
    const int t4   = lane & 3;
    const int n0   = blockIdx.x * 128;
    const int t    = blockIdx.y;
    const int dir  = blockIdx.z;

    const int m0 = (wid & 1) * 32;
    const int nw = (wid >> 1) * 32;

    const int ar = tid >> 2, ac = tid & 3;
    const int br = tid >> 1, bc = tid & 1;
    if (tid < 128) bias_s[tid] = bih[dir * 1024 + n0 + tid] + bhh[dir * 1024 + n0 + tid];

    const int La = lengths[ar];
    const int teff = dir ? ((t < La) ? (La - 1 - t) : t) : t;
    const uint4* a_p = (const uint4*)(g_h1h + ((size_t)ar * T_SEQ + teff) * 512) + ac;
    const uint4* b_p = (const uint4*)(g_w1h + ((size_t)(dir * 1024 + n0 + br)) * 512) + bc * 2;

    float acc[2][4][4];
    #pragma unroll
    for (int i = 0; i < 2; i++)
        #pragma unroll
        for (int j = 0; j < 4; j++)
            #pragma unroll
            for (int k = 0; k < 4; k++) acc[i][j][k] = 0.0f;

    uint4 va  = __ldg(a_p);
    uint4 vb0 = __ldg(b_p), vb1 = __ldg(b_p + 1);

    for (int kc = 0; kc < 16; kc++) {
        *reinterpret_cast<uint4*>(&Ax[ar * 20 + ac * 4]) = va;
        *reinterpret_cast<uint4*>(&Bx[br * 20 + bc * 8])     = vb0;
        *reinterpret_cast<uint4*>(&Bx[br * 20 + bc * 8 + 4]) = vb1;
        __syncthreads();

        if (kc + 1 < 16) {
            va  = __ldg(a_p + (kc + 1) * 4);
            vb0 = __ldg(b_p + (kc + 1) * 4);
            vb1 = __ldg(b_p + (kc + 1) * 4 + 1);
        }

        #pragma unroll
        for (int ks = 0; ks < 2; ks++) {
            uint32_t a[2][4];
            #pragma unroll
            for (int mf = 0; mf < 2; mf++) {
                int r = m0 + mf * 16 + g;
                a[mf][0] = Ax[r * 20 + ks * 8 + t4];
                a[mf][1] = Ax[(r + 8) * 20 + ks * 8 + t4];
                a[mf][2] = Ax[r * 20 + ks * 8 + t4 + 4];
                a[mf][3] = Ax[(r + 8) * 20 + ks * 8 + t4 + 4];
            }
            #pragma unroll
            for (int nf = 0; nf < 4; nf++) {
                int rn = nw + nf * 8 + g;
                uint32_t b0 = Bx[rn * 20 + ks * 8 + t4];
                uint32_t b1 = Bx[rn * 20 + ks * 8 + t4 + 4];
                mma_f16(acc[0][nf], a[0], b0, b1);
                mma_f16(acc[1][nf], a[1], b0, b1);
            }
        }
        __syncthreads();
    }

    float* gxp = g_gx + ((size_t)(dir * T_SEQ + t) * NB) * 1024 + n0;
    #pragma unroll
    for (int mf = 0; mf < 2; mf++) {
        int bi = m0 + mf * 16 + g;
        #pragma unroll
        for (int nf = 0; nf < 4; nf++) {
            int nn = nw + nf * 8 + t4 * 2;
            float bv0 = bias_s[nn], bv1 = bias_s[nn + 1];
            float2 v0 = make_float2(acc[mf][nf][0] + bv0, acc[mf][nf][1] + bv1);
            float2 v1 = make_float2(acc[mf][nf][2] + bv0, acc[mf][nf][3] + bv1);
            *reinterpret_cast<float2*>(gxp + (size_t)bi * 1024 + nn)       = v0;
            *reinterpret_cast<float2*>(gxp + (size_t)(bi + 8) * 1024 + nn) = v1;
        }
    }
}

// =====================================================================
// Head
// =====================================================================
__global__ void __launch_bounds__(256) head_fc1(const float* __restrict__ fc1_w,
                                                const float* __restrict__ fc1_b)
{
    __shared__ __align__(16) float fs[512];
    int b = blockIdx.x, n = threadIdx.x;
    for (int i = n; i < 512; i += 256) fs[i] = g_feat[b * 512 + i];
    __syncthreads();
    const float4* wp = reinterpret_cast<const float4*>(fc1_w + (size_t)n * 512);
    const float4* fp = reinterpret_cast<const float4*>(fs);
    float acc = fc1_b[n];
    #pragma unroll 4
    for (int k = 0; k < 128; k++) {
        float4 w4 = __ldg(wp + k);
        float4 f4 = fp[k];
        acc += w4.x * f4.x + w4.y * f4.y + w4.z * f4.z + w4.w * f4.w;
    }
    g_y[b * 256 + n] = fmaxf(acc, 0.0f);
}

__global__ void head_bn(const float* __restrict__ gamma, const float* __restrict__ beta)
{
    int n = threadIdx.x;
    float s = 0.0f, s2 = 0.0f;
    for (int b = 0; b < 64; b++) {
        float v = g_y[b * 256 + n];
        s += v; s2 += v * v;
    }
    float mean = s * 0.015625f;
    float var  = s2 * 0.015625f - mean * mean;
    float inv  = rsqrtf(var + 1e-5f);
    float ga = gamma[n] * inv, be = beta[n];
    for (int b = 0; b < 64; b++)
        g_y[b * 256 + n] = (g_y[b * 256 + n] - mean) * ga + be;
}

__global__ void __launch_bounds__(256) head_out(const float* __restrict__ W,
                                                const float* __restrict__ bias,
                                                float* __restrict__ out)
{
    __shared__ __align__(16) float ys[256];
    int b = blockIdx.x;
    ys[threadIdx.x] = g_y[b * 256 + threadIdx.x];
    __syncthreads();
    int o = threadIdx.x;
    if (o < 196) {
        const float4* wp = reinterpret_cast<const float4*>(W + (size_t)o * 256);
        const float4* yp = reinterpret_cast<const float4*>(ys);
        float acc = bias[o];
        #pragma unroll 4
        for (int k = 0; k < 64; k++) {
            float4 w4 = __ldg(wp + k);
            float4 y4 = yp[k];
            acc += w4.x * y4.x + w4.y * y4.y + w4.z * y4.z + w4.w * y4.w;
        }
        out[(size_t)b * 196 + o] = acc;
    }
}

// =====================================================================
extern "C" void kernel_launch(void* const* d_in, const int* in_sizes, int n_in,
                              void* d_out, int out_size)
{
    const float* x       = (const float*)d_in[0];
    const int*   lengths = (const int*)  d_in[1];
    const float* Wih0    = (const float*)d_in[2];
    const float* Whh0    = (const float*)d_in[3];
    const float* bih0    = (const float*)d_in[4];
    const float* bhh0    = (const float*)d_in[5];
    const float* Wih1    = (const float*)d_in[6];
    const float* Whh1    = (const float*)d_in[7];
    const float* bih1    = (const float*)d_in[8];
    const float* bhh1    = (const float*)d_in[9];
    const float* fc1_w   = (const float*)d_in[10];
    const float* fc1_b   = (const float*)d_in[11];
    const float* gamma   = (const float*)d_in[12];
    const float* beta    = (const float*)d_in[13];
    const float* fcow    = (const float*)d_in[14];
    const float* fcob    = (const float*)d_in[15];
    float* out = (float*)d_out;

    conv_w1<<<1024, 256>>>(Wih1);
    lstm_rec<0><<<64, 256>>>(x, lengths, Wih0, Whh0, bih0, bhh0);
    gx_mma<<<dim3(8, 1024, 2), 256>>>(lengths, bih1, bhh1);
    lstm_rec<1><<<64, 256>>>(x, lengths, Wih1, Whh1, bih1, bhh1);
    head_fc1<<<64, 256>>>(fc1_w, fc1_b);
    head_bn<<<1, 256>>>(gamma, beta);
    head_out<<<64, 256>>>(fcow, fcob, out);
}